// round 13
// baseline (speedup 1.0000x reference)
#include <cuda_runtime.h>
#include <cuda_bf16.h>
#include <math.h>
#include <mma.h>
#include <stdint.h>
using namespace nvcuda;

// ---------------- problem constants ----------------
static const int Bb   = 128;
static const int Ss   = 256;
static const int Dd   = 768;
static const int SPc  = 257;
static const int NROWS = Bb * SPc;           // 32896
static const int ARCc = 500;
static const int TAGc = 100;
static const int TOPKc = 8;
static const int ARCP = 512;
static const int TAGP = 128;
static const int PADR = 128;

// main GEMM tiling: 128x128 CTA tile, 4 warps (64x64), k-chunk 32, 3-stage
static const int ASTR = 40;
static const int BSTR = 136;
static const int APL  = 128 * ASTR;
static const int BPL  = 32 * BSTR;
static const int STG  = 2 * APL + 2 * BPL;
static const int NST  = 3;
static const int GSMEM = NST * STG * 2;       // 113664 B (2 CTAs/SM)

// bil tiling: 128x128 tile, 4 warps (64x64), k-chunk 32, 2-stage
static const int BPLN = 128 * 40;
static const int BSTG = 4 * BPLN;
static const int BILSMEM = 2 * BSTG * 2;      // 81920 B

// ---------------- fp32 scratch ----------------
__device__ float g_lg  [Bb * SPc * SPc];
__device__ float g_xw  [2 * NROWS * ARCP];
__device__ float g_xwt [2 * NROWS * TAGP];
__device__ float g_vals[NROWS * TOPKc];
__device__ int   g_idx [NROWS * TOPKc];
__device__ float g_dinv[NROWS];

// ---------------- bf16 hi/lo planes ----------------
__device__ __align__(16) __nv_bfloat16 g_xH[NROWS * Dd],  g_xL[NROWS * Dd];
__device__ __align__(16) __nv_bfloat16 g_arcH[(2 * NROWS + PADR) * ARCP], g_arcL[(2 * NROWS + PADR) * ARCP];
__device__ __align__(16) __nv_bfloat16 g_tagH[2 * NROWS * TAGP], g_tagL[2 * NROWS * TAGP];
__device__ __align__(16) __nv_bfloat16 g_t1H[(NROWS + PADR) * ARCP], g_t1L[(NROWS + PADR) * ARCP];
__device__ __align__(16) __nv_bfloat16 g_hH[2 * NROWS * ARCP], g_hL[2 * NROWS * ARCP];
__device__ __align__(16) __nv_bfloat16 g_thH[2 * NROWS * TAGP], g_thL[2 * NROWS * TAGP];
// weights [Kpad, Npad] row-major, padded, split
__device__ __align__(16) __nv_bfloat16 g_whaH[768 * 512], g_whaL[768 * 512];
__device__ __align__(16) __nv_bfloat16 g_wdaH[768 * 512], g_wdaL[768 * 512];
__device__ __align__(16) __nv_bfloat16 g_whtH[768 * 128], g_whtL[768 * 128];
__device__ __align__(16) __nv_bfloat16 g_wdtH[768 * 128], g_wdtL[768 * 128];
__device__ __align__(16) __nv_bfloat16 g_bilH[3 * 512 * 512], g_bilL[3 * 512 * 512];
__device__ __align__(16) __nv_bfloat16 g_c1aH[512 * 512], g_c1aL[512 * 512];
__device__ __align__(16) __nv_bfloat16 g_c2aH[512 * 512], g_c2aL[512 * 512];
__device__ __align__(16) __nv_bfloat16 g_c1rH[128 * 128], g_c1rL[128 * 128];
__device__ __align__(16) __nv_bfloat16 g_c2rH[128 * 128], g_c2rL[128 * 128];

__device__ __forceinline__ void splitbf(float v, __nv_bfloat16& h, __nv_bfloat16& l) {
    h = __float2bfloat16(v);
    l = __float2bfloat16(v - __bfloat162float(h));
}
__device__ __forceinline__ void cp16(void* dst, const void* src) {
    unsigned d = (unsigned)__cvta_generic_to_shared(dst);
    asm volatile("cp.async.cg.shared.global [%0], [%1], 16;" :: "r"(d), "l"(src));
}

// ---------------- fused weight pack ----------------
struct PJob {
    const float* src; __nv_bfloat16* hi; __nv_bfloat16* lo;
    int Wr, Wc, ldw, Np; long base, end;
};
struct PTab { PJob j[11]; };

__global__ void pack_all(PTab t, long total) {
    long i = (long)blockIdx.x * blockDim.x + threadIdx.x;
    if (i >= total) return;
#pragma unroll
    for (int q = 0; q < 11; q++) {
        if (i < t.j[q].end) {
            long loc = i - t.j[q].base;
            int r = (int)(loc / t.j[q].Np), c = (int)(loc % t.j[q].Np);
            float v = (r < t.j[q].Wr && c < t.j[q].Wc) ? t.j[q].src[(size_t)r * t.j[q].ldw + c] : 0.f;
            splitbf(v, t.j[q].hi[loc], t.j[q].lo[loc]);
            return;
        }
    }
}

__global__ void build_x_split(const float* __restrict__ inp, const float* __restrict__ sent,
                              __nv_bfloat16* __restrict__ xh, __nv_bfloat16* __restrict__ xl) {
    int n = blockIdx.x;
    int b = n / SPc, r = n % SPc;
    const float* src = (r == 0) ? sent : (inp + ((size_t)b * Ss + (r - 1)) * Dd);
    for (int f = threadIdx.x; f < Dd; f += blockDim.x)
        splitbf(src[f], xh[(size_t)n * Dd + f], xl[(size_t)n * Dd + f]);
}

// ---------------- main GEMM: 4 warps 64x64, 2 CTAs/SM, spill-free via unroll-1 A loop ----
__global__ void __launch_bounds__(128, 2)
gemm_bf16x3(const __nv_bfloat16* __restrict__ Ah, const __nv_bfloat16* __restrict__ Al, int lda,
            const __nv_bfloat16* __restrict__ Bh, const __nv_bfloat16* __restrict__ Bl, int ldb,
            float* __restrict__ Cf, int ldc,
            __nv_bfloat16* __restrict__ oH, __nv_bfloat16* __restrict__ oL,
            const float* __restrict__ bias, int validN, int act, int Kpad) {
    extern __shared__ __nv_bfloat16 sm[];
    int tid = threadIdx.x, warp = tid >> 5;
    int wm = warp & 1, wn = warp >> 1;
    int m0 = blockIdx.y << 7, n0 = blockIdx.x << 7;

    wmma::fragment<wmma::accumulator, 16, 16, 16, float> acc[4][4];
#pragma unroll
    for (int i = 0; i < 4; i++)
#pragma unroll
        for (int j = 0; j < 4; j++) wmma::fill_fragment(acc[i][j], 0.f);

    int nk = Kpad >> 5;

    auto load_stage = [&](int st, int k0) {
        __nv_bfloat16* a0 = sm + st * STG;
        __nv_bfloat16* a1 = a0 + APL;
        __nv_bfloat16* b0 = a1 + APL;
        __nv_bfloat16* b1 = b0 + BPL;
#pragma unroll
        for (int l = 0; l < 4; l++) {
            int id = tid + l * 128;
            int r = id >> 2, c = (id & 3) * 8;
            cp16(a0 + r * ASTR + c, Ah + (size_t)(m0 + r) * lda + k0 + c);
            cp16(a1 + r * ASTR + c, Al + (size_t)(m0 + r) * lda + k0 + c);
        }
#pragma unroll
        for (int l = 0; l < 4; l++) {
            int id = tid + l * 128;
            int r = id >> 4, c = (id & 15) * 8;
            cp16(b0 + r * BSTR + c, Bh + (size_t)(k0 + r) * ldb + n0 + c);
            cp16(b1 + r * BSTR + c, Bl + (size_t)(k0 + r) * ldb + n0 + c);
        }
        asm volatile("cp.async.commit_group;");
    };

    load_stage(0, 0);
    load_stage(1, 32);

    for (int kt = 0; kt < nk; kt++) {
        if (kt + 1 < nk) asm volatile("cp.async.wait_group 1;");
        else             asm volatile("cp.async.wait_group 0;");
        __syncthreads();
        if (kt + 2 < nk) load_stage((kt + 2) % NST, (kt + 2) << 5);

        int st = kt % NST;
        const __nv_bfloat16* a0 = sm + st * STG;
        const __nv_bfloat16* a1 = a0 + APL;
        const __nv_bfloat16* b0 = a1 + APL;
        const __nv_bfloat16* b1 = b0 + BPL;
#pragma unroll
        for (int ks = 0; ks < 2; ks++) {
            wmma::fragment<wmma::matrix_b, 16, 16, 16, __nv_bfloat16, wmma::row_major> fbh[4], fbl[4];
#pragma unroll
            for (int j = 0; j < 4; j++) {
                wmma::load_matrix_sync(fbh[j], b0 + (ks * 16) * BSTR + wn * 64 + j * 16, BSTR);
                wmma::load_matrix_sync(fbl[j], b1 + (ks * 16) * BSTR + wn * 64 + j * 16, BSTR);
            }
#pragma unroll 1
            for (int i = 0; i < 4; i++) {   // NOT unrolled: caps live A fragments at one pair
                wmma::fragment<wmma::matrix_a, 16, 16, 16, __nv_bfloat16, wmma::row_major> fah, fal;
                wmma::load_matrix_sync(fah, a0 + (wm * 64 + i * 16) * ASTR + ks * 16, ASTR);
                wmma::load_matrix_sync(fal, a1 + (wm * 64 + i * 16) * ASTR + ks * 16, ASTR);
#pragma unroll
                for (int j = 0; j < 4; j++) {
                    wmma::mma_sync(acc[i][j], fal, fbh[j], acc[i][j]);
                    wmma::mma_sync(acc[i][j], fah, fbl[j], acc[i][j]);
                    wmma::mma_sync(acc[i][j], fah, fbh[j], acc[i][j]);
                }
            }
        }
    }
    __syncthreads();

    float* Cs = (float*)sm;
#pragma unroll
    for (int i = 0; i < 4; i++)
#pragma unroll
        for (int j = 0; j < 4; j++)
            wmma::store_matrix_sync(Cs + (wm * 64 + i * 16) * 132 + wn * 64 + j * 16,
                                    acc[i][j], 132, wmma::mem_row_major);
    __syncthreads();
    {
        int c = tid;
        int gn = n0 + c;
        float bb = (bias && gn < validN) ? bias[gn] : 0.f;
#pragma unroll 8
        for (int r = 0; r < 128; r++) {
            float v = Cs[r * 132 + c] + bb;
            if (act) v = (v > 0.f) ? v : expm1f(v);
            size_t o = (size_t)(m0 + r) * ldc + gn;
            if (Cf) Cf[o] = v;
            if (oH) { __nv_bfloat16 h, l2; splitbf(v, h, l2); oH[o] = h; oL[o] = l2; }
        }
    }
}

// ---------------- batched bilinear NT (full tiles; same unroll-1 trick) ----------------
__global__ void __launch_bounds__(128, 2)
bil_nt_bf16x3(const __nv_bfloat16* __restrict__ t1h, const __nv_bfloat16* __restrict__ t1l,
              const __nv_bfloat16* __restrict__ dah, const __nv_bfloat16* __restrict__ dal,
              const float* __restrict__ bilb, int kidx, float* __restrict__ Cout) {
    extern __shared__ __nv_bfloat16 sm[];
    int tid = threadIdx.x, warp = tid >> 5;
    int wm = warp & 1, wn = warp >> 1;
    int bz = blockIdx.z;
    int i0 = blockIdx.y << 7, j0 = blockIdx.x << 7;
    size_t arow = (size_t)bz * SPc + i0;
    size_t brow = (size_t)bz * SPc + j0;

    wmma::fragment<wmma::accumulator, 16, 16, 16, float> acc[4][4];
#pragma unroll
    for (int i = 0; i < 4; i++)
#pragma unroll
        for (int j = 0; j < 4; j++) wmma::fill_fragment(acc[i][j], 0.f);

    auto load_stage = [&](int st, int k0) {
        __nv_bfloat16* a0 = sm + st * BSTG;
        __nv_bfloat16* a1 = a0 + BPLN;
        __nv_bfloat16* b0 = a1 + BPLN;
        __nv_bfloat16* b1 = b0 + BPLN;
#pragma unroll
        for (int l = 0; l < 4; l++) {
            int id = tid + l * 128;
            int r = id >> 2, c = (id & 3) * 8;
            cp16(a0 + r * 40 + c, t1h + (arow + r) * ARCP + k0 + c);
            cp16(a1 + r * 40 + c, t1l + (arow + r) * ARCP + k0 + c);
            cp16(b0 + r * 40 + c, dah + (brow + r) * ARCP + k0 + c);
            cp16(b1 + r * 40 + c, dal + (brow + r) * ARCP + k0 + c);
        }
        asm volatile("cp.async.commit_group;");
    };

    const int nk = ARCP >> 5;
    load_stage(0, 0);
    load_stage(1, 32);

    for (int kt = 0; kt < nk; kt++) {
        if (kt + 1 < nk) asm volatile("cp.async.wait_group 1;");
        else             asm volatile("cp.async.wait_group 0;");
        __syncthreads();
        int st = kt & 1;
        const __nv_bfloat16* a0 = sm + st * BSTG;
        const __nv_bfloat16* a1 = a0 + BPLN;
        const __nv_bfloat16* b0 = a1 + BPLN;
        const __nv_bfloat16* b1 = b0 + BPLN;
#pragma unroll
        for (int ks = 0; ks < 2; ks++) {
            wmma::fragment<wmma::matrix_b, 16, 16, 16, __nv_bfloat16, wmma::col_major> fbh[4], fbl[4];
#pragma unroll
            for (int j = 0; j < 4; j++) {
                wmma::load_matrix_sync(fbh[j], b0 + (wn * 64 + j * 16) * 40 + ks * 16, 40);
                wmma::load_matrix_sync(fbl[j], b1 + (wn * 64 + j * 16) * 40 + ks * 16, 40);
            }
#pragma unroll 1
            for (int i = 0; i < 4; i++) {
                wmma::fragment<wmma::matrix_a, 16, 16, 16, __nv_bfloat16, wmma::row_major> fah, fal;
                wmma::load_matrix_sync(fah, a0 + (wm * 64 + i * 16) * 40 + ks * 16, 40);
                wmma::load_matrix_sync(fal, a1 + (wm * 64 + i * 16) * 40 + ks * 16, 40);
#pragma unroll
                for (int j = 0; j < 4; j++) {
                    wmma::mma_sync(acc[i][j], fal, fbh[j], acc[i][j]);
                    wmma::mma_sync(acc[i][j], fah, fbl[j], acc[i][j]);
                    wmma::mma_sync(acc[i][j], fah, fbh[j], acc[i][j]);
                }
            }
        }
        __syncthreads();
        if (kt + 2 < nk) load_stage(st, (kt + 2) << 5);
    }

    float* Cs = (float*)sm;
    __syncthreads();
#pragma unroll
    for (int i = 0; i < 4; i++)
#pragma unroll
        for (int j = 0; j < 4; j++)
            wmma::store_matrix_sync(Cs + (wm * 64 + i * 16) * 132 + wn * 64 + j * 16,
                                    acc[i][j], 132, wmma::mem_row_major);
    __syncthreads();
    {
        int c = tid;
        int oj = j0 + c;
        float bb = bilb[kidx];
        for (int r = 0; r < 128; r++) {
            int oi = i0 + r;
            size_t brow2 = ((size_t)bz * SPc + oi) * ARCP + ARCc;
            float rowb = __bfloat162float(t1h[brow2]) + __bfloat162float(t1l[brow2]);
            Cout[((size_t)bz * SPc + oi) * SPc + oj] = Cs[r * 132 + c] + rowb + bb;
        }
    }
}

// edge: lg[b, i, 256] and lg[b, 256, j]
__global__ void bil_edge(const __nv_bfloat16* __restrict__ t1h, const __nv_bfloat16* __restrict__ t1l,
                         const __nv_bfloat16* __restrict__ dah, const __nv_bfloat16* __restrict__ dal,
                         const float* __restrict__ bilb, int kidx, float* __restrict__ Cout) {
    int wg = blockIdx.x * 8 + (threadIdx.x >> 5);
    int lane = threadIdx.x & 31;
    int total = Bb * 2 * SPc;
    if (wg >= total) return;
    int b = wg / (2 * SPc);
    int d = wg % (2 * SPc);
    int i = (d < SPc) ? d : 256;
    int j = (d < SPc) ? 256 : (d - SPc);
    const __nv_bfloat16* th = t1h + ((size_t)b * SPc + i) * ARCP;
    const __nv_bfloat16* tl = t1l + ((size_t)b * SPc + i) * ARCP;
    const __nv_bfloat16* dh = dah + ((size_t)b * SPc + j) * ARCP;
    const __nv_bfloat16* dl = dal + ((size_t)b * SPc + j) * ARCP;
    float s = 0.f;
#pragma unroll
    for (int t = 0; t < 16; t++) {
        int c = lane + 32 * t;
        float av = __bfloat162float(th[c]) + __bfloat162float(tl[c]);
        float bv = __bfloat162float(dh[c]) + __bfloat162float(dl[c]);
        s += av * bv;
    }
#pragma unroll
    for (int off = 16; off > 0; off >>= 1) s += __shfl_xor_sync(0xffffffffu, s, off);
    if (lane == 0) {
        float rowb = __bfloat162float(th[ARCc]) + __bfloat162float(tl[ARCc]);
        Cout[((size_t)b * SPc + i) * SPc + j] = s + rowb + bilb[kidx];
    }
}

// ---------------- fused softmax + top-8 + dinv ----------------
__global__ void smax_topk(const float* __restrict__ lg) {
    int row = blockIdx.x * 8 + (threadIdx.x >> 5);
    int lane = threadIdx.x & 31;
    if (row >= NROWS) return;
    const float* p = lg + (size_t)row * SPc;
    float v[9];
    float mx = -INFINITY;
#pragma unroll
    for (int t = 0; t < 9; t++) {
        int c = lane + 32 * t;
        v[t] = (c < SPc) ? p[c] : -INFINITY;
        mx = fmaxf(mx, v[t]);
    }
#pragma unroll
    for (int off = 16; off > 0; off >>= 1) mx = fmaxf(mx, __shfl_xor_sync(0xffffffffu, mx, off));
    float s = 0.f;
#pragma unroll
    for (int t = 0; t < 9; t++) {
        int c = lane + 32 * t;
        if (c < SPc) { v[t] = expf(v[t] - mx); s += v[t]; } else v[t] = -INFINITY;
    }
#pragma unroll
    for (int off = 16; off > 0; off >>= 1) s += __shfl_xor_sync(0xffffffffu, s, off);
    float inv = 1.f / s;
#pragma unroll
    for (int t = 0; t < 9; t++) {
        int c = lane + 32 * t;
        if (c < SPc) v[t] *= inv;
    }
    float acc8 = 0.f;
    for (int it = 0; it < TOPKc; it++) {
        float bv = -INFINITY; int bi = 0x7fffffff;
#pragma unroll
        for (int t = 0; t < 9; t++) {
            int c = lane + 32 * t;
            if (v[t] > bv || (v[t] == bv && c < bi)) { bv = v[t]; bi = c; }
        }
#pragma unroll
        for (int off = 16; off > 0; off >>= 1) {
            float ov = __shfl_down_sync(0xffffffffu, bv, off);
            int oi   = __shfl_down_sync(0xffffffffu, bi, off);
            if (ov > bv || (ov == bv && oi < bi)) { bv = ov; bi = oi; }
        }
        bv = __shfl_sync(0xffffffffu, bv, 0);
        bi = __shfl_sync(0xffffffffu, bi, 0);
        if (lane == 0) { g_vals[(size_t)row * TOPKc + it] = bv; g_idx[(size_t)row * TOPKc + it] = bi; }
        acc8 += bv;
        if (lane == (bi & 31)) v[bi >> 5] = -INFINITY;
    }
    if (lane == 0) g_dinv[row] = rsqrtf(1.f + acc8);
}

// ---------------- GCN aggregate + ELU + split (float4) ----------------
__global__ void gcn_agg_split(const float* __restrict__ xw, const float* __restrict__ bias,
                              __nv_bfloat16* __restrict__ outh, __nv_bfloat16* __restrict__ outl,
                              int Fp, int Fv, int act) {
    int gid = blockIdx.x;
    int i = gid % NROWS;
    int stream = gid / NROWS;
    int b = i / SPc;
    __shared__ float cf[TOPKc];
    __shared__ int   ss[TOPKc];
    float di = g_dinv[i];
    if (threadIdx.x < TOPKc) {
        int k = threadIdx.x;
        int srow = b * SPc + g_idx[(size_t)i * TOPKc + k];
        ss[k] = stream * NROWS + srow;
        cf[k] = di * g_vals[(size_t)i * TOPKc + k] * g_dinv[srow];
    }
    __syncthreads();
    float selfc = di * di;
    int nf4 = Fp >> 2;
    const float4* x4 = (const float4*)xw;
    for (int f = threadIdx.x; f < nf4; f += blockDim.x) {
        float4 a = x4[(size_t)gid * nf4 + f];
        float4 acc = make_float4(selfc * a.x, selfc * a.y, selfc * a.z, selfc * a.w);
#pragma unroll
        for (int k = 0; k < TOPKc; k++) {
            float4 sv = x4[(size_t)ss[k] * nf4 + f];
            float c = cf[k];
            acc.x += c * sv.x; acc.y += c * sv.y; acc.z += c * sv.z; acc.w += c * sv.w;
        }
        if (f * 4 < Fv) {
            float4 bv = ((const float4*)bias)[f];
            acc.x += bv.x; acc.y += bv.y; acc.z += bv.z; acc.w += bv.w;
        }
        if (act) {
            acc.x = (acc.x > 0.f) ? acc.x : expm1f(acc.x);
            acc.y = (acc.y > 0.f) ? acc.y : expm1f(acc.y);
            acc.z = (acc.z > 0.f) ? acc.z : expm1f(acc.z);
            acc.w = (acc.w > 0.f) ? acc.w : expm1f(acc.w);
        }
        size_t o = (size_t)gid * Fp + f * 4;
        __nv_bfloat16 h0, l0, h1, l1, h2, l2, h3, l3;
        splitbf(acc.x, h0, l0); splitbf(acc.y, h1, l1);
        splitbf(acc.z, h2, l2); splitbf(acc.w, h3, l3);
        outh[o] = h0; outh[o + 1] = h1; outh[o + 2] = h2; outh[o + 3] = h3;
        outl[o] = l0; outl[o + 1] = l1; outl[o + 2] = l2; outl[o + 3] = l3;
    }
}

// strided copy reconstructing fp32 from hi+lo planes
__global__ void copy_hl(const __nv_bfloat16* __restrict__ h, const __nv_bfloat16* __restrict__ l,
                        float* __restrict__ dst, int ld, int valid, int rows) {
    long i = (long)blockIdx.x * blockDim.x + threadIdx.x;
    long total = (long)rows * valid;
    if (i >= total) return;
    int n = (int)(i / valid), f = (int)(i % valid);
    size_t o = (size_t)n * ld + f;
    dst[i] = __bfloat162float(h[o]) + __bfloat162float(l[o]);
}

// ---------------- host ----------------
template <typename T>
static T* sym(const void* s) { void* p; cudaGetSymbolAddress(&p, s); return (T*)p; }

static void run_gemm(cudaStream_t st, const __nv_bfloat16* Ah, const __nv_bfloat16* Al, int lda,
                     const __nv_bfloat16* Bh, const __nv_bfloat16* Bl, int Npad,
                     float* Cf, __nv_bfloat16* oH, __nv_bfloat16* oL,
                     const float* bias, int validN, int act,
                     int M, int Kpad) {
    dim3 grid(Npad >> 7, M >> 7);
    gemm_bf16x3<<<grid, 128, GSMEM, st>>>(Ah, Al, lda, Bh, Bl, Npad, Cf, Npad, oH, oL, bias, validN, act, Kpad);
}

extern "C" void kernel_launch(void* const* d_in, const int* in_sizes, int n_in,
                              void* d_out, int out_size) {
    const float* inputs = (const float*)d_in[0];
    const float* sent   = (const float*)d_in[5];
    const float* W_ha = (const float*)d_in[6];  const float* b_ha = (const float*)d_in[7];
    const float* W_da = (const float*)d_in[8];  const float* b_da = (const float*)d_in[9];
    const float* W_ht = (const float*)d_in[10]; const float* b_ht = (const float*)d_in[11];
    const float* W_dt = (const float*)d_in[12]; const float* b_dt = (const float*)d_in[13];
    const float* bilW = (const float*)d_in[14]; const float* bilb = (const float*)d_in[15];
    const float* c1aW = (const float*)d_in[16]; const float* c1ab = (const float*)d_in[17];
    const float* c2aW = (const float*)d_in[18]; const float* c2ab = (const float*)d_in[19];
    const float* c1rW = (const float*)d_in[20]; const float* c1rb = (const float*)d_in[21];
    const float* c2rW = (const float*)d_in[22]; const float* c2rb = (const float*)d_in[23];
    float* out = (float*)d_out;

    static cudaStream_t s2 = nullptr;
    static cudaEvent_t ev0, evT0, evT1, evJ;
    if (!s2) {
        cudaStreamCreateWithFlags(&s2, cudaStreamNonBlocking);
        cudaEventCreateWithFlags(&ev0, cudaEventDisableTiming);
        cudaEventCreateWithFlags(&evT0, cudaEventDisableTiming);
        cudaEventCreateWithFlags(&evT1, cudaEventDisableTiming);
        cudaEventCreateWithFlags(&evJ, cudaEventDisableTiming);
    }
    cudaStream_t ms = 0;

    cudaFuncSetAttribute(gemm_bf16x3, cudaFuncAttributeMaxDynamicSharedMemorySize, GSMEM);
    cudaFuncSetAttribute(bil_nt_bf16x3, cudaFuncAttributeMaxDynamicSharedMemorySize, BILSMEM);

    float* lg   = sym<float>(g_lg);
    float* xw   = sym<float>(g_xw);
    float* xwt  = sym<float>(g_xwt);
    __nv_bfloat16 *xH = sym<__nv_bfloat16>(g_xH), *xL = sym<__nv_bfloat16>(g_xL);
    __nv_bfloat16 *arcH = sym<__nv_bfloat16>(g_arcH), *arcL = sym<__nv_bfloat16>(g_arcL);
    __nv_bfloat16 *tagH = sym<__nv_bfloat16>(g_tagH), *tagL = sym<__nv_bfloat16>(g_tagL);
    __nv_bfloat16 *t1H = sym<__nv_bfloat16>(g_t1H), *t1L = sym<__nv_bfloat16>(g_t1L);
    __nv_bfloat16 *hH = sym<__nv_bfloat16>(g_hH), *hL = sym<__nv_bfloat16>(g_hL);
    __nv_bfloat16 *thH = sym<__nv_bfloat16>(g_thH), *thL = sym<__nv_bfloat16>(g_thL);
    __nv_bfloat16 *whaH = sym<__nv_bfloat16>(g_whaH), *whaL = sym<__nv_bfloat16>(g_whaL);
    __nv_bfloat16 *wdaH = sym<__nv_bfloat16>(g_wdaH), *wdaL = sym<__nv_bfloat16>(g_wdaL);
    __nv_bfloat16 *whtH = sym<__nv_bfloat16>(g_whtH), *whtL = sym<__nv_bfloat16>(g_whtL);
    __nv_bfloat16 *wdtH = sym<__nv_bfloat16>(g_wdtH), *wdtL = sym<__nv_bfloat16>(g_wdtL);
    __nv_bfloat16 *bilH = sym<__nv_bfloat16>(g_bilH), *bilL = sym<__nv_bfloat16>(g_bilL);
    __nv_bfloat16 *c1aH = sym<__nv_bfloat16>(g_c1aH), *c1aL = sym<__nv_bfloat16>(g_c1aL);
    __nv_bfloat16 *c2aH = sym<__nv_bfloat16>(g_c2aH), *c2aL = sym<__nv_bfloat16>(g_c2aL);
    __nv_bfloat16 *c1rH = sym<__nv_bfloat16>(g_c1rH), *c1rL = sym<__nv_bfloat16>(g_c1rL);
    __nv_bfloat16 *c2rH = sym<__nv_bfloat16>(g_c2rH), *c2rL = sym<__nv_bfloat16>(g_c2rL);

    __nv_bfloat16 *haH = arcH, *haL = arcL;
    __nv_bfloat16 *daH = arcH + (size_t)NROWS * ARCP, *daL = arcL + (size_t)NROWS * ARCP;
    __nv_bfloat16 *htH = tagH, *htL = tagL;
    __nv_bfloat16 *dtH = tagH + (size_t)NROWS * TAGP, *dtL = tagL + (size_t)NROWS * TAGP;

    // --- fused weight pack ---
    {
        PTab t;
        long base = 0;
        auto add = [&](int q, const float* src, __nv_bfloat16* hi, __nv_bfloat16* lo,
                       int Wr, int Wc, int ldw, int Kp, int Np) {
            t.j[q] = {src, hi, lo, Wr, Wc, ldw, Np, base, base + (long)Kp * Np};
            base += (long)Kp * Np;
        };
        add(0, W_ha, whaH, whaL, 768, 500, 500, 768, 512);
        add(1, W_da, wdaH, wdaL, 768, 500, 500, 768, 512);
        add(2, W_ht, whtH, whtL, 768, 100, 100, 768, 128);
        add(3, W_dt, wdtH, wdtL, 768, 100, 100, 768, 128);
        for (int k = 0; k < 3; k++)
            add(4 + k, bilW + (size_t)k * 501 * 501, bilH + (size_t)k * 512 * 512,
                bilL + (size_t)k * 512 * 512, 500, 501, 501, 512, 512);
        add(7, c1aW, c1aH, c1aL, 500, 500, 500, 512, 512);
        add(8, c2aW, c2aH, c2aL, 500, 500, 500, 512, 512);
        add(9, c1rW, c1rH, c1rL, 100, 100, 100, 128, 128);
        add(10, c2rW, c2rH, c2rL, 100, 100, 100, 128, 128);
        pack_all<<<(unsigned)((base + 255) / 256), 256, 0, ms>>>(t, base);
    }

    // --- x ---
    build_x_split<<<NROWS, 256, 0, ms>>>(inputs, sent, xH, xL);
    cudaEventRecord(ev0, ms);
    cudaStreamWaitEvent(s2, ev0, 0);

    run_gemm(ms, xH, xL, Dd, whaH, whaL, ARCP, nullptr, haH, haL, b_ha, ARCc, 1, NROWS, Dd);
    run_gemm(ms, xH, xL, Dd, wdaH, wdaL, ARCP, nullptr, daH, daL, b_da, ARCc, 1, NROWS, Dd);
    run_gemm(s2, xH, xL, Dd, whtH, whtL, TAGP, nullptr, htH, htL, b_ht, TAGc, 1, NROWS, Dd);
    run_gemm(s2, xH, xL, Dd, wdtH, wdtL, TAGP, nullptr, dtH, dtL, b_dt, TAGc, 1, NROWS, Dd);

    dim3 bilgrid(2, 2, Bb);
    int edgegrid = (Bb * 2 * SPc + 7) / 8;
    int smgrid = (NROWS + 7) / 8;
    cudaEvent_t evT[2] = {evT0, evT1};

    for (int k = 0; k < 2; k++) {
        run_gemm(ms, haH, haL, ARCP, bilH + (size_t)k * 512 * 512, bilL + (size_t)k * 512 * 512, ARCP,
                 nullptr, t1H, t1L, bilW + (size_t)k * 501 * 501 + (size_t)500 * 501, 501, 0, NROWS, ARCP);
        bil_nt_bf16x3<<<bilgrid, 128, BILSMEM, ms>>>(t1H, t1L, daH, daL, bilb, k, lg);
        bil_edge<<<edgegrid, 256, 0, ms>>>(t1H, t1L, daH, daL, bilb, k, lg);
        smax_topk<<<smgrid, 256, 0, ms>>>(lg);
        cudaEventRecord(evT[k], ms);
        cudaStreamWaitEvent(s2, evT[k], 0);

        // arc chain (main)
        run_gemm(ms, arcH, arcL, ARCP, c1aH, c1aL, ARCP, xw, nullptr, nullptr, nullptr, 0, 0, 2 * NROWS, ARCP);
        gcn_agg_split<<<2 * NROWS, 128, 0, ms>>>(xw, c1ab, hH, hL, ARCP, ARCc, 1);
        run_gemm(ms, hH, hL, ARCP, c2aH, c2aL, ARCP, xw, nullptr, nullptr, nullptr, 0, 0, 2 * NROWS, ARCP);
        gcn_agg_split<<<2 * NROWS, 128, 0, ms>>>(xw, c2ab, arcH, arcL, ARCP, ARCc, 0);
        // tag chain (s2)
        run_gemm(s2, tagH, tagL, TAGP, c1rH, c1rL, TAGP, xwt, nullptr, nullptr, nullptr, 0, 0, 2 * NROWS, TAGP);
        gcn_agg_split<<<2 * NROWS, 128, 0, s2>>>(xwt, c1rb, thH, thL, TAGP, TAGc, 1);
        run_gemm(s2, thH, thL, TAGP, c2rH, c2rL, TAGP, xwt, nullptr, nullptr, nullptr, 0, 0, 2 * NROWS, TAGP);
        gcn_agg_split<<<2 * NROWS, 128, 0, s2>>>(xwt, c2rb, tagH, tagL, TAGP, TAGc, 0);
    }

    // final bilinear -> d_out (main) ; tag output copies (s2)
    long arcN = (long)Bb * SPc * SPc;
    long tagN = (long)NROWS * TAGc;
    run_gemm(ms, haH, haL, ARCP, bilH + (size_t)2 * 512 * 512, bilL + (size_t)2 * 512 * 512, ARCP,
             nullptr, t1H, t1L, bilW + (size_t)2 * 501 * 501 + (size_t)500 * 501, 501, 0, NROWS, ARCP);
    bil_nt_bf16x3<<<bilgrid, 128, BILSMEM, ms>>>(t1H, t1L, daH, daL, bilb, 2, out);
    bil_edge<<<edgegrid, 256, 0, ms>>>(t1H, t1L, daH, daL, bilb, 2, out);

    copy_hl<<<(unsigned)((tagN + 255) / 256), 256, 0, s2>>>(htH, htL, out + arcN, TAGP, TAGc, NROWS);
    copy_hl<<<(unsigned)((tagN + 255) / 256), 256, 0, s2>>>(dtH, dtL, out + arcN + tagN, TAGP, TAGc, NROWS);

    cudaEventRecord(evJ, s2);
    cudaStreamWaitEvent(ms, evJ, 0);
}

// round 14
// speedup vs baseline: 2.0762x; 2.0762x over previous
#include <cuda_runtime.h>
#include <cuda_bf16.h>
#include <math.h>
#include <mma.h>
#include <stdint.h>
using namespace nvcuda;

// ---------------- problem constants ----------------
static const int Bb   = 128;
static const int Ss   = 256;
static const int Dd   = 768;
static const int SPc  = 257;
static const int NROWS = Bb * SPc;           // 32896
static const int ARCc = 500;
static const int TAGc = 100;
static const int TOPKc = 8;
static const int ARCP = 512;
static const int TAGP = 128;
static const int PADR = 128;

// main GEMM tiling: 128x128 CTA tile, 4 warps (64x64), k-chunk 32, 3-stage
static const int ASTR = 40;
static const int BSTR = 136;
static const int APL  = 128 * ASTR;
static const int BPL  = 32 * BSTR;
static const int STG  = 2 * APL + 2 * BPL;
static const int NST  = 3;
static const int GSMEM = NST * STG * 2;       // 113664 B (2 CTAs/SM)

// bil tiling: 128x128 tile, 4 warps (64x64), k-chunk 32, 2-stage
static const int BPLN = 128 * 40;
static const int BSTG = 4 * BPLN;
static const int BILSMEM = 2 * BSTG * 2;      // 81920 B

// ---------------- fp32 scratch ----------------
__device__ float g_lg  [Bb * SPc * SPc];
__device__ float g_xw  [2 * NROWS * ARCP];
__device__ float g_xwt [2 * NROWS * TAGP];
__device__ float g_vals[NROWS * TOPKc];
__device__ int   g_idx [NROWS * TOPKc];
__device__ float g_dinv[NROWS];

// ---------------- bf16 hi/lo planes ----------------
__device__ __align__(16) __nv_bfloat16 g_xH[NROWS * Dd],  g_xL[NROWS * Dd];
__device__ __align__(16) __nv_bfloat16 g_arcH[(2 * NROWS + PADR) * ARCP], g_arcL[(2 * NROWS + PADR) * ARCP];
__device__ __align__(16) __nv_bfloat16 g_tagH[2 * NROWS * TAGP], g_tagL[2 * NROWS * TAGP];
__device__ __align__(16) __nv_bfloat16 g_t1H[(NROWS + PADR) * ARCP], g_t1L[(NROWS + PADR) * ARCP];
__device__ __align__(16) __nv_bfloat16 g_hH[2 * NROWS * ARCP], g_hL[2 * NROWS * ARCP];
__device__ __align__(16) __nv_bfloat16 g_thH[2 * NROWS * TAGP], g_thL[2 * NROWS * TAGP];
// weights [Kpad, Npad] row-major, padded, split
__device__ __align__(16) __nv_bfloat16 g_whaH[768 * 512], g_whaL[768 * 512];
__device__ __align__(16) __nv_bfloat16 g_wdaH[768 * 512], g_wdaL[768 * 512];
__device__ __align__(16) __nv_bfloat16 g_whtH[768 * 128], g_whtL[768 * 128];
__device__ __align__(16) __nv_bfloat16 g_wdtH[768 * 128], g_wdtL[768 * 128];
__device__ __align__(16) __nv_bfloat16 g_bilH[3 * 512 * 512], g_bilL[3 * 512 * 512];
__device__ __align__(16) __nv_bfloat16 g_c1aH[512 * 512], g_c1aL[512 * 512];
__device__ __align__(16) __nv_bfloat16 g_c2aH[512 * 512], g_c2aL[512 * 512];
__device__ __align__(16) __nv_bfloat16 g_c1rH[128 * 128], g_c1rL[128 * 128];
__device__ __align__(16) __nv_bfloat16 g_c2rH[128 * 128], g_c2rL[128 * 128];

__device__ __forceinline__ void splitbf(float v, __nv_bfloat16& h, __nv_bfloat16& l) {
    h = __float2bfloat16(v);
    l = __float2bfloat16(v - __bfloat162float(h));
}
__device__ __forceinline__ void cp16(void* dst, const void* src) {
    unsigned d = (unsigned)__cvta_generic_to_shared(dst);
    asm volatile("cp.async.cg.shared.global [%0], [%1], 16;" :: "r"(d), "l"(src));
}

// ---------------- fused weight pack ----------------
struct PJob {
    const float* src; __nv_bfloat16* hi; __nv_bfloat16* lo;
    int Wr, Wc, ldw, Np; long base, end;
};
struct PTab { PJob j[11]; };

__global__ void pack_all(PTab t, long total) {
    long i = (long)blockIdx.x * blockDim.x + threadIdx.x;
    if (i >= total) return;
#pragma unroll
    for (int q = 0; q < 11; q++) {
        if (i < t.j[q].end) {
            long loc = i - t.j[q].base;
            int r = (int)(loc / t.j[q].Np), c = (int)(loc % t.j[q].Np);
            float v = (r < t.j[q].Wr && c < t.j[q].Wc) ? t.j[q].src[(size_t)r * t.j[q].ldw + c] : 0.f;
            splitbf(v, t.j[q].hi[loc], t.j[q].lo[loc]);
            return;
        }
    }
}

__global__ void build_x_split(const float* __restrict__ inp, const float* __restrict__ sent,
                              __nv_bfloat16* __restrict__ xh, __nv_bfloat16* __restrict__ xl) {
    int n = blockIdx.x;
    int b = n / SPc, r = n % SPc;
    const float* src = (r == 0) ? sent : (inp + ((size_t)b * Ss + (r - 1)) * Dd);
    for (int f = threadIdx.x; f < Dd; f += blockDim.x)
        splitbf(src[f], xh[(size_t)n * Dd + f], xl[(size_t)n * Dd + f]);
}

// ---------------- main GEMM (r12 config restored; pointer-increment addressing) ----------
__global__ void __launch_bounds__(128, 2)
gemm_bf16x3(const __nv_bfloat16* __restrict__ Ah, const __nv_bfloat16* __restrict__ Al, int lda,
            const __nv_bfloat16* __restrict__ Bh, const __nv_bfloat16* __restrict__ Bl, int ldb,
            float* __restrict__ Cf, int ldc,
            __nv_bfloat16* __restrict__ oH, __nv_bfloat16* __restrict__ oL,
            const float* __restrict__ bias, int validN, int act, int Kpad) {
    extern __shared__ __nv_bfloat16 sm[];
    int tid = threadIdx.x, warp = tid >> 5;
    int wm = warp & 1, wn = warp >> 1;
    int m0 = blockIdx.y << 7, n0 = blockIdx.x << 7;

    wmma::fragment<wmma::accumulator, 16, 16, 16, float> acc[4][4];
#pragma unroll
    for (int i = 0; i < 4; i++)
#pragma unroll
        for (int j = 0; j < 4; j++) wmma::fill_fragment(acc[i][j], 0.f);

    int nk = Kpad >> 5;

    // per-thread incrementing global pointers (advance 32 per k-chunk)
    int ra = tid >> 2, ca = (tid & 3) * 8;
    int rb = tid >> 4, cb = (tid & 15) * 8;
    const __nv_bfloat16* pAh = Ah + (size_t)(m0 + ra) * lda + ca;
    const __nv_bfloat16* pAl = Al + (size_t)(m0 + ra) * lda + ca;
    const __nv_bfloat16* pBh = Bh + (size_t)rb * ldb + n0 + cb;
    const __nv_bfloat16* pBl = Bl + (size_t)rb * ldb + n0 + cb;

    auto load_stage = [&](int st, int kc) {
        __nv_bfloat16* a0 = sm + st * STG;
        __nv_bfloat16* a1 = a0 + APL;
        __nv_bfloat16* b0 = a1 + APL;
        __nv_bfloat16* b1 = b0 + BPL;
        size_t koffA = (size_t)kc << 5;
        size_t koffB = ((size_t)kc << 5) * ldb;
#pragma unroll
        for (int l = 0; l < 4; l++) {
            int r = ra + l * 32;
            cp16(a0 + r * ASTR + ca, pAh + (size_t)l * 32 * lda + koffA);
            cp16(a1 + r * ASTR + ca, pAl + (size_t)l * 32 * lda + koffA);
        }
#pragma unroll
        for (int l = 0; l < 4; l++) {
            int r = rb + l * 8;
            cp16(b0 + r * BSTR + cb, pBh + (size_t)l * 8 * ldb + koffB);
            cp16(b1 + r * BSTR + cb, pBl + (size_t)l * 8 * ldb + koffB);
        }
        asm volatile("cp.async.commit_group;");
    };

    load_stage(0, 0);
    load_stage(1, 1);

    for (int kt = 0; kt < nk; kt++) {
        if (kt + 1 < nk) asm volatile("cp.async.wait_group 1;");
        else             asm volatile("cp.async.wait_group 0;");
        __syncthreads();
        if (kt + 2 < nk) load_stage((kt + 2) % NST, kt + 2);

        int st = kt % NST;
        const __nv_bfloat16* a0 = sm + st * STG;
        const __nv_bfloat16* a1 = a0 + APL;
        const __nv_bfloat16* b0 = a1 + APL;
        const __nv_bfloat16* b1 = b0 + BPL;
#pragma unroll
        for (int ks = 0; ks < 2; ks++) {
            wmma::fragment<wmma::matrix_a, 16, 16, 16, __nv_bfloat16, wmma::row_major> fah[4], fal[4];
            wmma::fragment<wmma::matrix_b, 16, 16, 16, __nv_bfloat16, wmma::row_major> fbh[4], fbl[4];
#pragma unroll
            for (int i = 0; i < 4; i++) {
                wmma::load_matrix_sync(fah[i], a0 + (wm * 64 + i * 16) * ASTR + ks * 16, ASTR);
                wmma::load_matrix_sync(fal[i], a1 + (wm * 64 + i * 16) * ASTR + ks * 16, ASTR);
            }
#pragma unroll
            for (int j = 0; j < 4; j++) {
                wmma::load_matrix_sync(fbh[j], b0 + (ks * 16) * BSTR + wn * 64 + j * 16, BSTR);
                wmma::load_matrix_sync(fbl[j], b1 + (ks * 16) * BSTR + wn * 64 + j * 16, BSTR);
            }
#pragma unroll
            for (int i = 0; i < 4; i++)
#pragma unroll
                for (int j = 0; j < 4; j++) {
                    wmma::mma_sync(acc[i][j], fal[i], fbh[j], acc[i][j]);
                    wmma::mma_sync(acc[i][j], fah[i], fbl[j], acc[i][j]);
                    wmma::mma_sync(acc[i][j], fah[i], fbh[j], acc[i][j]);
                }
        }
    }
    __syncthreads();

    float* Cs = (float*)sm;
#pragma unroll
    for (int i = 0; i < 4; i++)
#pragma unroll
        for (int j = 0; j < 4; j++)
            wmma::store_matrix_sync(Cs + (wm * 64 + i * 16) * 132 + wn * 64 + j * 16,
                                    acc[i][j], 132, wmma::mem_row_major);
    __syncthreads();
    {
        int c = tid;
        int gn = n0 + c;
        float bb = (bias && gn < validN) ? bias[gn] : 0.f;
#pragma unroll 8
        for (int r = 0; r < 128; r++) {
            float v = Cs[r * 132 + c] + bb;
            if (act) v = (v > 0.f) ? v : expm1f(v);
            size_t o = (size_t)(m0 + r) * ldc + gn;
            if (Cf) Cf[o] = v;
            if (oH) { __nv_bfloat16 h, l2; splitbf(v, h, l2); oH[o] = h; oL[o] = l2; }
        }
    }
}

// ---------------- batched bilinear NT (r12 config restored) ----------------
__global__ void __launch_bounds__(128, 2)
bil_nt_bf16x3(const __nv_bfloat16* __restrict__ t1h, const __nv_bfloat16* __restrict__ t1l,
              const __nv_bfloat16* __restrict__ dah, const __nv_bfloat16* __restrict__ dal,
              const float* __restrict__ bilb, int kidx, float* __restrict__ Cout) {
    extern __shared__ __nv_bfloat16 sm[];
    int tid = threadIdx.x, warp = tid >> 5;
    int wm = warp & 1, wn = warp >> 1;
    int bz = blockIdx.z;
    int i0 = blockIdx.y << 7, j0 = blockIdx.x << 7;
    size_t arow = (size_t)bz * SPc + i0;
    size_t brow = (size_t)bz * SPc + j0;

    wmma::fragment<wmma::accumulator, 16, 16, 16, float> acc[4][4];
#pragma unroll
    for (int i = 0; i < 4; i++)
#pragma unroll
        for (int j = 0; j < 4; j++) wmma::fill_fragment(acc[i][j], 0.f);

    auto load_stage = [&](int st, int k0) {
        __nv_bfloat16* a0 = sm + st * BSTG;
        __nv_bfloat16* a1 = a0 + BPLN;
        __nv_bfloat16* b0 = a1 + BPLN;
        __nv_bfloat16* b1 = b0 + BPLN;
#pragma unroll
        for (int l = 0; l < 4; l++) {
            int id = tid + l * 128;
            int r = id >> 2, c = (id & 3) * 8;
            cp16(a0 + r * 40 + c, t1h + (arow + r) * ARCP + k0 + c);
            cp16(a1 + r * 40 + c, t1l + (arow + r) * ARCP + k0 + c);
            cp16(b0 + r * 40 + c, dah + (brow + r) * ARCP + k0 + c);
            cp16(b1 + r * 40 + c, dal + (brow + r) * ARCP + k0 + c);
        }
        asm volatile("cp.async.commit_group;");
    };

    const int nk = ARCP >> 5;
    load_stage(0, 0);
    load_stage(1, 32);

    for (int kt = 0; kt < nk; kt++) {
        if (kt + 1 < nk) asm volatile("cp.async.wait_group 1;");
        else             asm volatile("cp.async.wait_group 0;");
        __syncthreads();
        int st = kt & 1;
        const __nv_bfloat16* a0 = sm + st * BSTG;
        const __nv_bfloat16* a1 = a0 + BPLN;
        const __nv_bfloat16* b0 = a1 + BPLN;
        const __nv_bfloat16* b1 = b0 + BPLN;
#pragma unroll
        for (int ks = 0; ks < 2; ks++) {
            wmma::fragment<wmma::matrix_a, 16, 16, 16, __nv_bfloat16, wmma::row_major> fah[4], fal[4];
            wmma::fragment<wmma::matrix_b, 16, 16, 16, __nv_bfloat16, wmma::col_major> fbh[4], fbl[4];
#pragma unroll
            for (int i = 0; i < 4; i++) {
                wmma::load_matrix_sync(fah[i], a0 + (wm * 64 + i * 16) * 40 + ks * 16, 40);
                wmma::load_matrix_sync(fal[i], a1 + (wm * 64 + i * 16) * 40 + ks * 16, 40);
            }
#pragma unroll
            for (int j = 0; j < 4; j++) {
                wmma::load_matrix_sync(fbh[j], b0 + (wn * 64 + j * 16) * 40 + ks * 16, 40);
                wmma::load_matrix_sync(fbl[j], b1 + (wn * 64 + j * 16) * 40 + ks * 16, 40);
            }
#pragma unroll
            for (int i = 0; i < 4; i++)
#pragma unroll
                for (int j = 0; j < 4; j++) {
                    wmma::mma_sync(acc[i][j], fal[i], fbh[j], acc[i][j]);
                    wmma::mma_sync(acc[i][j], fah[i], fbl[j], acc[i][j]);
                    wmma::mma_sync(acc[i][j], fah[i], fbh[j], acc[i][j]);
                }
        }
        __syncthreads();
        if (kt + 2 < nk) load_stage(st, (kt + 2) << 5);
    }

    float* Cs = (float*)sm;
    __syncthreads();
#pragma unroll
    for (int i = 0; i < 4; i++)
#pragma unroll
        for (int j = 0; j < 4; j++)
            wmma::store_matrix_sync(Cs + (wm * 64 + i * 16) * 132 + wn * 64 + j * 16,
                                    acc[i][j], 132, wmma::mem_row_major);
    __syncthreads();
    {
        int c = tid;
        int oj = j0 + c;
        float bb = bilb[kidx];
        for (int r = 0; r < 128; r++) {
            int oi = i0 + r;
            size_t brow2 = ((size_t)bz * SPc + oi) * ARCP + ARCc;
            float rowb = __bfloat162float(t1h[brow2]) + __bfloat162float(t1l[brow2]);
            Cout[((size_t)bz * SPc + oi) * SPc + oj] = Cs[r * 132 + c] + rowb + bb;
        }
    }
}

// edge: lg[b, i, 256] and lg[b, 256, j]
__global__ void bil_edge(const __nv_bfloat16* __restrict__ t1h, const __nv_bfloat16* __restrict__ t1l,
                         const __nv_bfloat16* __restrict__ dah, const __nv_bfloat16* __restrict__ dal,
                         const float* __restrict__ bilb, int kidx, float* __restrict__ Cout) {
    int wg = blockIdx.x * 8 + (threadIdx.x >> 5);
    int lane = threadIdx.x & 31;
    int total = Bb * 2 * SPc;
    if (wg >= total) return;
    int b = wg / (2 * SPc);
    int d = wg % (2 * SPc);
    int i = (d < SPc) ? d : 256;
    int j = (d < SPc) ? 256 : (d - SPc);
    const __nv_bfloat16* th = t1h + ((size_t)b * SPc + i) * ARCP;
    const __nv_bfloat16* tl = t1l + ((size_t)b * SPc + i) * ARCP;
    const __nv_bfloat16* dh = dah + ((size_t)b * SPc + j) * ARCP;
    const __nv_bfloat16* dl = dal + ((size_t)b * SPc + j) * ARCP;
    float s = 0.f;
#pragma unroll
    for (int t = 0; t < 16; t++) {
        int c = lane + 32 * t;
        float av = __bfloat162float(th[c]) + __bfloat162float(tl[c]);
        float bv = __bfloat162float(dh[c]) + __bfloat162float(dl[c]);
        s += av * bv;
    }
#pragma unroll
    for (int off = 16; off > 0; off >>= 1) s += __shfl_xor_sync(0xffffffffu, s, off);
    if (lane == 0) {
        float rowb = __bfloat162float(th[ARCc]) + __bfloat162float(tl[ARCc]);
        Cout[((size_t)b * SPc + i) * SPc + j] = s + rowb + bilb[kidx];
    }
}

// ---------------- fused softmax + top-8 + dinv ----------------
__global__ void smax_topk(const float* __restrict__ lg) {
    int row = blockIdx.x * 8 + (threadIdx.x >> 5);
    int lane = threadIdx.x & 31;
    if (row >= NROWS) return;
    const float* p = lg + (size_t)row * SPc;
    float v[9];
    float mx = -INFINITY;
#pragma unroll
    for (int t = 0; t < 9; t++) {
        int c = lane + 32 * t;
        v[t] = (c < SPc) ? p[c] : -INFINITY;
        mx = fmaxf(mx, v[t]);
    }
#pragma unroll
    for (int off = 16; off > 0; off >>= 1) mx = fmaxf(mx, __shfl_xor_sync(0xffffffffu, mx, off));
    float s = 0.f;
#pragma unroll
    for (int t = 0; t < 9; t++) {
        int c = lane + 32 * t;
        if (c < SPc) { v[t] = expf(v[t] - mx); s += v[t]; } else v[t] = -INFINITY;
    }
#pragma unroll
    for (int off = 16; off > 0; off >>= 1) s += __shfl_xor_sync(0xffffffffu, s, off);
    float inv = 1.f / s;
#pragma unroll
    for (int t = 0; t < 9; t++) {
        int c = lane + 32 * t;
        if (c < SPc) v[t] *= inv;
    }
    float acc8 = 0.f;
    for (int it = 0; it < TOPKc; it++) {
        float bv = -INFINITY; int bi = 0x7fffffff;
#pragma unroll
        for (int t = 0; t < 9; t++) {
            int c = lane + 32 * t;
            if (v[t] > bv || (v[t] == bv && c < bi)) { bv = v[t]; bi = c; }
        }
#pragma unroll
        for (int off = 16; off > 0; off >>= 1) {
            float ov = __shfl_down_sync(0xffffffffu, bv, off);
            int oi   = __shfl_down_sync(0xffffffffu, bi, off);
            if (ov > bv || (ov == bv && oi < bi)) { bv = ov; bi = oi; }
        }
        bv = __shfl_sync(0xffffffffu, bv, 0);
        bi = __shfl_sync(0xffffffffu, bi, 0);
        if (lane == 0) { g_vals[(size_t)row * TOPKc + it] = bv; g_idx[(size_t)row * TOPKc + it] = bi; }
        acc8 += bv;
        if (lane == (bi & 31)) v[bi >> 5] = -INFINITY;
    }
    if (lane == 0) g_dinv[row] = rsqrtf(1.f + acc8);
}

// ---------------- GCN aggregate + ELU + split (float4) ----------------
__global__ void gcn_agg_split(const float* __restrict__ xw, const float* __restrict__ bias,
                              __nv_bfloat16* __restrict__ outh, __nv_bfloat16* __restrict__ outl,
                              int Fp, int Fv, int act) {
    int gid = blockIdx.x;
    int i = gid % NROWS;
    int stream = gid / NROWS;
    int b = i / SPc;
    __shared__ float cf[TOPKc];
    __shared__ int   ss[TOPKc];
    float di = g_dinv[i];
    if (threadIdx.x < TOPKc) {
        int k = threadIdx.x;
        int srow = b * SPc + g_idx[(size_t)i * TOPKc + k];
        ss[k] = stream * NROWS + srow;
        cf[k] = di * g_vals[(size_t)i * TOPKc + k] * g_dinv[srow];
    }
    __syncthreads();
    float selfc = di * di;
    int nf4 = Fp >> 2;
    const float4* x4 = (const float4*)xw;
    for (int f = threadIdx.x; f < nf4; f += blockDim.x) {
        float4 a = x4[(size_t)gid * nf4 + f];
        float4 acc = make_float4(selfc * a.x, selfc * a.y, selfc * a.z, selfc * a.w);
#pragma unroll
        for (int k = 0; k < TOPKc; k++) {
            float4 sv = x4[(size_t)ss[k] * nf4 + f];
            float c = cf[k];
            acc.x += c * sv.x; acc.y += c * sv.y; acc.z += c * sv.z; acc.w += c * sv.w;
        }
        if (f * 4 < Fv) {
            float4 bv = ((const float4*)bias)[f];
            acc.x += bv.x; acc.y += bv.y; acc.z += bv.z; acc.w += bv.w;
        }
        if (act) {
            acc.x = (acc.x > 0.f) ? acc.x : expm1f(acc.x);
            acc.y = (acc.y > 0.f) ? acc.y : expm1f(acc.y);
            acc.z = (acc.z > 0.f) ? acc.z : expm1f(acc.z);
            acc.w = (acc.w > 0.f) ? acc.w : expm1f(acc.w);
        }
        size_t o = (size_t)gid * Fp + f * 4;
        __nv_bfloat16 h0, l0, h1, l1, h2, l2, h3, l3;
        splitbf(acc.x, h0, l0); splitbf(acc.y, h1, l1);
        splitbf(acc.z, h2, l2); splitbf(acc.w, h3, l3);
        outh[o] = h0; outh[o + 1] = h1; outh[o + 2] = h2; outh[o + 3] = h3;
        outl[o] = l0; outl[o + 1] = l1; outl[o + 2] = l2; outl[o + 3] = l3;
    }
}

// strided copy reconstructing fp32 from hi+lo planes
__global__ void copy_hl(const __nv_bfloat16* __restrict__ h, const __nv_bfloat16* __restrict__ l,
                        float* __restrict__ dst, int ld, int valid, int rows) {
    long i = (long)blockIdx.x * blockDim.x + threadIdx.x;
    long total = (long)rows * valid;
    if (i >= total) return;
    int n = (int)(i / valid), f = (int)(i % valid);
    size_t o = (size_t)n * ld + f;
    dst[i] = __bfloat162float(h[o]) + __bfloat162float(l[o]);
}

// ---------------- host ----------------
template <typename T>
static T* sym(const void* s) { void* p; cudaGetSymbolAddress(&p, s); return (T*)p; }

static void run_gemm(cudaStream_t st, const __nv_bfloat16* Ah, const __nv_bfloat16* Al, int lda,
                     const __nv_bfloat16* Bh, const __nv_bfloat16* Bl, int Npad,
                     float* Cf, __nv_bfloat16* oH, __nv_bfloat16* oL,
                     const float* bias, int validN, int act,
                     int M, int Kpad) {
    dim3 grid(Npad >> 7, M >> 7);
    gemm_bf16x3<<<grid, 128, GSMEM, st>>>(Ah, Al, lda, Bh, Bl, Npad, Cf, Npad, oH, oL, bias, validN, act, Kpad);
}

extern "C" void kernel_launch(void* const* d_in, const int* in_sizes, int n_in,
                              void* d_out, int out_size) {
    const float* inputs = (const float*)d_in[0];
    const float* sent   = (const float*)d_in[5];
    const float* W_ha = (const float*)d_in[6];  const float* b_ha = (const float*)d_in[7];
    const float* W_da = (const float*)d_in[8];  const float* b_da = (const float*)d_in[9];
    const float* W_ht = (const float*)d_in[10]; const float* b_ht = (const float*)d_in[11];
    const float* W_dt = (const float*)d_in[12]; const float* b_dt = (const float*)d_in[13];
    const float* bilW = (const float*)d_in[14]; const float* bilb = (const float*)d_in[15];
    const float* c1aW = (const float*)d_in[16]; const float* c1ab = (const float*)d_in[17];
    const float* c2aW = (const float*)d_in[18]; const float* c2ab = (const float*)d_in[19];
    const float* c1rW = (const float*)d_in[20]; const float* c1rb = (const float*)d_in[21];
    const float* c2rW = (const float*)d_in[22]; const float* c2rb = (const float*)d_in[23];
    float* out = (float*)d_out;

    static cudaStream_t s2 = nullptr;
    static cudaEvent_t ev0, evT0, evT1, evJ;
    if (!s2) {
        cudaStreamCreateWithFlags(&s2, cudaStreamNonBlocking);
        cudaEventCreateWithFlags(&ev0, cudaEventDisableTiming);
        cudaEventCreateWithFlags(&evT0, cudaEventDisableTiming);
        cudaEventCreateWithFlags(&evT1, cudaEventDisableTiming);
        cudaEventCreateWithFlags(&evJ, cudaEventDisableTiming);
    }
    cudaStream_t ms = 0;

    cudaFuncSetAttribute(gemm_bf16x3, cudaFuncAttributeMaxDynamicSharedMemorySize, GSMEM);
    cudaFuncSetAttribute(bil_nt_bf16x3, cudaFuncAttributeMaxDynamicSharedMemorySize, BILSMEM);

    float* lg   = sym<float>(g_lg);
    float* xw   = sym<float>(g_xw);
    float* xwt  = sym<float>(g_xwt);
    __nv_bfloat16 *xH = sym<__nv_bfloat16>(g_xH), *xL = sym<__nv_bfloat16>(g_xL);
    __nv_bfloat16 *arcH = sym<__nv_bfloat16>(g_arcH), *arcL = sym<__nv_bfloat16>(g_arcL);
    __nv_bfloat16 *tagH = sym<__nv_bfloat16>(g_tagH), *tagL = sym<__nv_bfloat16>(g_tagL);
    __nv_bfloat16 *t1H = sym<__nv_bfloat16>(g_t1H), *t1L = sym<__nv_bfloat16>(g_t1L);
    __nv_bfloat16 *hH = sym<__nv_bfloat16>(g_hH), *hL = sym<__nv_bfloat16>(g_hL);
    __nv_bfloat16 *thH = sym<__nv_bfloat16>(g_thH), *thL = sym<__nv_bfloat16>(g_thL);
    __nv_bfloat16 *whaH = sym<__nv_bfloat16>(g_whaH), *whaL = sym<__nv_bfloat16>(g_whaL);
    __nv_bfloat16 *wdaH = sym<__nv_bfloat16>(g_wdaH), *wdaL = sym<__nv_bfloat16>(g_wdaL);
    __nv_bfloat16 *whtH = sym<__nv_bfloat16>(g_whtH), *whtL = sym<__nv_bfloat16>(g_whtL);
    __nv_bfloat16 *wdtH = sym<__nv_bfloat16>(g_wdtH), *wdtL = sym<__nv_bfloat16>(g_wdtL);
    __nv_bfloat16 *bilH = sym<__nv_bfloat16>(g_bilH), *bilL = sym<__nv_bfloat16>(g_bilL);
    __nv_bfloat16 *c1aH = sym<__nv_bfloat16>(g_c1aH), *c1aL = sym<__nv_bfloat16>(g_c1aL);
    __nv_bfloat16 *c2aH = sym<__nv_bfloat16>(g_c2aH), *c2aL = sym<__nv_bfloat16>(g_c2aL);
    __nv_bfloat16 *c1rH = sym<__nv_bfloat16>(g_c1rH), *c1rL = sym<__nv_bfloat16>(g_c1rL);
    __nv_bfloat16 *c2rH = sym<__nv_bfloat16>(g_c2rH), *c2rL = sym<__nv_bfloat16>(g_c2rL);

    __nv_bfloat16 *haH = arcH, *haL = arcL;
    __nv_bfloat16 *daH = arcH + (size_t)NROWS * ARCP, *daL = arcL + (size_t)NROWS * ARCP;
    __nv_bfloat16 *htH = tagH, *htL = tagL;
    __nv_bfloat16 *dtH = tagH + (size_t)NROWS * TAGP, *dtL = tagL + (size_t)NROWS * TAGP;

    // --- fused weight pack ---
    {
        PTab t;
        long base = 0;
        auto add = [&](int q, const float* src, __nv_bfloat16* hi, __nv_bfloat16* lo,
                       int Wr, int Wc, int ldw, int Kp, int Np) {
            t.j[q] = {src, hi, lo, Wr, Wc, ldw, Np, base, base + (long)Kp * Np};
            base += (long)Kp * Np;
        };
        add(0, W_ha, whaH, whaL, 768, 500, 500, 768, 512);
        add(1, W_da, wdaH, wdaL, 768, 500, 500, 768, 512);
        add(2, W_ht, whtH, whtL, 768, 100, 100, 768, 128);
        add(3, W_dt, wdtH, wdtL, 768, 100, 100, 768, 128);
        for (int k = 0; k < 3; k++)
            add(4 + k, bilW + (size_t)k * 501 * 501, bilH + (size_t)k * 512 * 512,
                bilL + (size_t)k * 512 * 512, 500, 501, 501, 512, 512);
        add(7, c1aW, c1aH, c1aL, 500, 500, 500, 512, 512);
        add(8, c2aW, c2aH, c2aL, 500, 500, 500, 512, 512);
        add(9, c1rW, c1rH, c1rL, 100, 100, 100, 128, 128);
        add(10, c2rW, c2rH, c2rL, 100, 100, 100, 128, 128);
        pack_all<<<(unsigned)((base + 255) / 256), 256, 0, ms>>>(t, base);
    }

    // --- x ---
    build_x_split<<<NROWS, 256, 0, ms>>>(inputs, sent, xH, xL);
    cudaEventRecord(ev0, ms);
    cudaStreamWaitEvent(s2, ev0, 0);

    run_gemm(ms, xH, xL, Dd, whaH, whaL, ARCP, nullptr, haH, haL, b_ha, ARCc, 1, NROWS, Dd);
    run_gemm(ms, xH, xL, Dd, wdaH, wdaL, ARCP, nullptr, daH, daL, b_da, ARCc, 1, NROWS, Dd);
    run_gemm(s2, xH, xL, Dd, whtH, whtL, TAGP, nullptr, htH, htL, b_ht, TAGc, 1, NROWS, Dd);
    run_gemm(s2, xH, xL, Dd, wdtH, wdtL, TAGP, nullptr, dtH, dtL, b_dt, TAGc, 1, NROWS, Dd);

    dim3 bilgrid(2, 2, Bb);
    int edgegrid = (Bb * 2 * SPc + 7) / 8;
    int smgrid = (NROWS + 7) / 8;
    cudaEvent_t evT[2] = {evT0, evT1};

    for (int k = 0; k < 2; k++) {
        run_gemm(ms, haH, haL, ARCP, bilH + (size_t)k * 512 * 512, bilL + (size_t)k * 512 * 512, ARCP,
                 nullptr, t1H, t1L, bilW + (size_t)k * 501 * 501 + (size_t)500 * 501, 501, 0, NROWS, ARCP);
        bil_nt_bf16x3<<<bilgrid, 128, BILSMEM, ms>>>(t1H, t1L, daH, daL, bilb, k, lg);
        bil_edge<<<edgegrid, 256, 0, ms>>>(t1H, t1L, daH, daL, bilb, k, lg);
        smax_topk<<<smgrid, 256, 0, ms>>>(lg);
        cudaEventRecord(evT[k], ms);
        cudaStreamWaitEvent(s2, evT[k], 0);

        // arc chain (main)
        run_gemm(ms, arcH, arcL, ARCP, c1aH, c1aL, ARCP, xw, nullptr, nullptr, nullptr, 0, 0, 2 * NROWS, ARCP);
        gcn_agg_split<<<2 * NROWS, 128, 0, ms>>>(xw, c1ab, hH, hL, ARCP, ARCc, 1);
        run_gemm(ms, hH, hL, ARCP, c2aH, c2aL, ARCP, xw, nullptr, nullptr, nullptr, 0, 0, 2 * NROWS, ARCP);
        gcn_agg_split<<<2 * NROWS, 128, 0, ms>>>(xw, c2ab, arcH, arcL, ARCP, ARCc, 0);
        // tag chain (s2)
        run_gemm(s2, tagH, tagL, TAGP, c1rH, c1rL, TAGP, xwt, nullptr, nullptr, nullptr, 0, 0, 2 * NROWS, TAGP);
        gcn_agg_split<<<2 * NROWS, 128, 0, s2>>>(xwt, c1rb, thH, thL, TAGP, TAGc, 1);
        run_gemm(s2, thH, thL, TAGP, c2rH, c2rL, TAGP, xwt, nullptr, nullptr, nullptr, 0, 0, 2 * NROWS, TAGP);
        gcn_agg_split<<<2 * NROWS, 128, 0, s2>>>(xwt, c2rb, tagH, tagL, TAGP, TAGc, 0);
    }

    // final bilinear -> d_out (main) ; tag output copies (s2)
    long arcN = (long)Bb * SPc * SPc;
    long tagN = (long)NROWS * TAGc;
    run_gemm(ms, haH, haL, ARCP, bilH + (size_t)2 * 512 * 512, bilL + (size_t)2 * 512 * 512, ARCP,
             nullptr, t1H, t1L, bilW + (size_t)2 * 501 * 501 + (size_t)500 * 501, 501, 0, NROWS, ARCP);
    bil_nt_bf16x3<<<bilgrid, 128, BILSMEM, ms>>>(t1H, t1L, daH, daL, bilb, 2, out);
    bil_edge<<<edgegrid, 256, 0, ms>>>(t1H, t1L, daH, daL, bilb, 2, out);

    copy_hl<<<(unsigned)((tagN + 255) / 256), 256, 0, s2>>>(htH, htL, out + arcN, TAGP, TAGc, NROWS);
    copy_hl<<<(unsigned)((tagN + 255) / 256), 256, 0, s2>>>(dtH, dtL, out + arcN + tagN, TAGP, TAGc, NROWS);

    cudaEventRecord(evJ, s2);
    cudaStreamWaitEvent(ms, evJ, 0);
}

// round 15
// speedup vs baseline: 2.0850x; 1.0042x over previous
#include <cuda_runtime.h>
#include <cuda_bf16.h>
#include <math.h>
#include <mma.h>
#include <stdint.h>
using namespace nvcuda;

// ---------------- problem constants ----------------
static const int Bb   = 128;
static const int Ss   = 256;
static const int Dd   = 768;
static const int SPc  = 257;
static const int NROWS = Bb * SPc;           // 32896
static const int ARCc = 500;
static const int TAGc = 100;
static const int TOPKc = 8;
static const int ARCP = 512;
static const int TAGP = 128;
static const int PADR = 128;

// main GEMM tiling: 128x128 CTA tile, 4 warps (64x64), k-chunk 32, 3-stage
static const int ASTR = 40;
static const int BSTR = 136;
static const int APL  = 128 * ASTR;
static const int BPL  = 32 * BSTR;
static const int STG  = 2 * APL + 2 * BPL;
static const int NST  = 3;
static const int GSMEM = NST * STG * 2;       // 113664 B (2 CTAs/SM)

// bil tiling: 128x128 tile, 4 warps (64x64), k-chunk 32, 2-stage
static const int BPLN = 128 * 40;
static const int BSTG = 4 * BPLN;
static const int BILSMEM = 2 * BSTG * 2;      // 81920 B

// ---------------- fp32 scratch ----------------
__device__ float g_lg  [Bb * SPc * SPc];
__device__ float g_xw  [2 * NROWS * ARCP];
__device__ float g_xwt [2 * NROWS * TAGP];
__device__ float g_vals[NROWS * TOPKc];
__device__ int   g_idx [NROWS * TOPKc];
__device__ float g_dinv[NROWS];

// ---------------- bf16 hi/lo planes ----------------
__device__ __align__(16) __nv_bfloat16 g_xH[NROWS * Dd],  g_xL[NROWS * Dd];
__device__ __align__(16) __nv_bfloat16 g_arcH[(2 * NROWS + PADR) * ARCP], g_arcL[(2 * NROWS + PADR) * ARCP];
__device__ __align__(16) __nv_bfloat16 g_tagH[2 * NROWS * TAGP], g_tagL[2 * NROWS * TAGP];
__device__ __align__(16) __nv_bfloat16 g_t1H[(NROWS + PADR) * ARCP], g_t1L[(NROWS + PADR) * ARCP];
__device__ __align__(16) __nv_bfloat16 g_hH[2 * NROWS * ARCP], g_hL[2 * NROWS * ARCP];
__device__ __align__(16) __nv_bfloat16 g_thH[2 * NROWS * TAGP], g_thL[2 * NROWS * TAGP];
// weights [Kpad, Npad] row-major, padded, split
__device__ __align__(16) __nv_bfloat16 g_whaH[768 * 512], g_whaL[768 * 512];
__device__ __align__(16) __nv_bfloat16 g_wdaH[768 * 512], g_wdaL[768 * 512];
__device__ __align__(16) __nv_bfloat16 g_whtH[768 * 128], g_whtL[768 * 128];
__device__ __align__(16) __nv_bfloat16 g_wdtH[768 * 128], g_wdtL[768 * 128];
__device__ __align__(16) __nv_bfloat16 g_bilH[3 * 512 * 512], g_bilL[3 * 512 * 512];
__device__ __align__(16) __nv_bfloat16 g_c1aH[512 * 512], g_c1aL[512 * 512];
__device__ __align__(16) __nv_bfloat16 g_c2aH[512 * 512], g_c2aL[512 * 512];
__device__ __align__(16) __nv_bfloat16 g_c1rH[128 * 128], g_c1rL[128 * 128];
__device__ __align__(16) __nv_bfloat16 g_c2rH[128 * 128], g_c2rL[128 * 128];

__device__ __forceinline__ void splitbf(float v, __nv_bfloat16& h, __nv_bfloat16& l) {
    h = __float2bfloat16(v);
    l = __float2bfloat16(v - __bfloat162float(h));
}
__device__ __forceinline__ void cp16(void* dst, const void* src) {
    unsigned d = (unsigned)__cvta_generic_to_shared(dst);
    asm volatile("cp.async.cg.shared.global [%0], [%1], 16;" :: "r"(d), "l"(src));
}

// ---------------- fused weight pack ----------------
struct PJob {
    const float* src; __nv_bfloat16* hi; __nv_bfloat16* lo;
    int Wr, Wc, ldw, Np; long base, end;
};
struct PTab { PJob j[11]; };

__global__ void pack_all(PTab t, long total) {
    long i = (long)blockIdx.x * blockDim.x + threadIdx.x;
    if (i >= total) return;
#pragma unroll
    for (int q = 0; q < 11; q++) {
        if (i < t.j[q].end) {
            long loc = i - t.j[q].base;
            int r = (int)(loc / t.j[q].Np), c = (int)(loc % t.j[q].Np);
            float v = (r < t.j[q].Wr && c < t.j[q].Wc) ? t.j[q].src[(size_t)r * t.j[q].ldw + c] : 0.f;
            splitbf(v, t.j[q].hi[loc], t.j[q].lo[loc]);
            return;
        }
    }
}

__global__ void build_x_split(const float* __restrict__ inp, const float* __restrict__ sent,
                              __nv_bfloat16* __restrict__ xh, __nv_bfloat16* __restrict__ xl) {
    int n = blockIdx.x;
    int b = n / SPc, r = n % SPc;
    const float* src = (r == 0) ? sent : (inp + ((size_t)b * Ss + (r - 1)) * Dd);
    for (int f = threadIdx.x; f < Dd; f += blockDim.x)
        splitbf(src[f], xh[(size_t)n * Dd + f], xl[(size_t)n * Dd + f]);
}

// ---------------- main GEMM (r12 config restored; pointer-increment addressing) ----------
__global__ void __launch_bounds__(128, 2)
gemm_bf16x3(const __nv_bfloat16* __restrict__ Ah, const __nv_bfloat16* __restrict__ Al, int lda,
            const __nv_bfloat16* __restrict__ Bh, const __nv_bfloat16* __restrict__ Bl, int ldb,
            float* __restrict__ Cf, int ldc,
            __nv_bfloat16* __restrict__ oH, __nv_bfloat16* __restrict__ oL,
            const float* __restrict__ bias, int validN, int act, int Kpad) {
    extern __shared__ __nv_bfloat16 sm[];
    int tid = threadIdx.x, warp = tid >> 5;
    int wm = warp & 1, wn = warp >> 1;
    int m0 = blockIdx.y << 7, n0 = blockIdx.x << 7;

    wmma::fragment<wmma::accumulator, 16, 16, 16, float> acc[4][4];
#pragma unroll
    for (int i = 0; i < 4; i++)
#pragma unroll
        for (int j = 0; j < 4; j++) wmma::fill_fragment(acc[i][j], 0.f);

    int nk = Kpad >> 5;

    // per-thread incrementing global pointers (advance 32 per k-chunk)
    int ra = tid >> 2, ca = (tid & 3) * 8;
    int rb = tid >> 4, cb = (tid & 15) * 8;
    const __nv_bfloat16* pAh = Ah + (size_t)(m0 + ra) * lda + ca;
    const __nv_bfloat16* pAl = Al + (size_t)(m0 + ra) * lda + ca;
    const __nv_bfloat16* pBh = Bh + (size_t)rb * ldb + n0 + cb;
    const __nv_bfloat16* pBl = Bl + (size_t)rb * ldb + n0 + cb;

    auto load_stage = [&](int st, int kc) {
        __nv_bfloat16* a0 = sm + st * STG;
        __nv_bfloat16* a1 = a0 + APL;
        __nv_bfloat16* b0 = a1 + APL;
        __nv_bfloat16* b1 = b0 + BPL;
        size_t koffA = (size_t)kc << 5;
        size_t koffB = ((size_t)kc << 5) * ldb;
#pragma unroll
        for (int l = 0; l < 4; l++) {
            int r = ra + l * 32;
            cp16(a0 + r * ASTR + ca, pAh + (size_t)l * 32 * lda + koffA);
            cp16(a1 + r * ASTR + ca, pAl + (size_t)l * 32 * lda + koffA);
        }
#pragma unroll
        for (int l = 0; l < 4; l++) {
            int r = rb + l * 8;
            cp16(b0 + r * BSTR + cb, pBh + (size_t)l * 8 * ldb + koffB);
            cp16(b1 + r * BSTR + cb, pBl + (size_t)l * 8 * ldb + koffB);
        }
        asm volatile("cp.async.commit_group;");
    };

    load_stage(0, 0);
    load_stage(1, 1);

    for (int kt = 0; kt < nk; kt++) {
        if (kt + 1 < nk) asm volatile("cp.async.wait_group 1;");
        else             asm volatile("cp.async.wait_group 0;");
        __syncthreads();
        if (kt + 2 < nk) load_stage((kt + 2) % NST, kt + 2);

        int st = kt % NST;
        const __nv_bfloat16* a0 = sm + st * STG;
        const __nv_bfloat16* a1 = a0 + APL;
        const __nv_bfloat16* b0 = a1 + APL;
        const __nv_bfloat16* b1 = b0 + BPL;
#pragma unroll
        for (int ks = 0; ks < 2; ks++) {
            wmma::fragment<wmma::matrix_a, 16, 16, 16, __nv_bfloat16, wmma::row_major> fah[4], fal[4];
            wmma::fragment<wmma::matrix_b, 16, 16, 16, __nv_bfloat16, wmma::row_major> fbh[4], fbl[4];
#pragma unroll
            for (int i = 0; i < 4; i++) {
                wmma::load_matrix_sync(fah[i], a0 + (wm * 64 + i * 16) * ASTR + ks * 16, ASTR);
                wmma::load_matrix_sync(fal[i], a1 + (wm * 64 + i * 16) * ASTR + ks * 16, ASTR);
            }
#pragma unroll
            for (int j = 0; j < 4; j++) {
                wmma::load_matrix_sync(fbh[j], b0 + (ks * 16) * BSTR + wn * 64 + j * 16, BSTR);
                wmma::load_matrix_sync(fbl[j], b1 + (ks * 16) * BSTR + wn * 64 + j * 16, BSTR);
            }
#pragma unroll
            for (int i = 0; i < 4; i++)
#pragma unroll
                for (int j = 0; j < 4; j++) {
                    wmma::mma_sync(acc[i][j], fal[i], fbh[j], acc[i][j]);
                    wmma::mma_sync(acc[i][j], fah[i], fbl[j], acc[i][j]);
                    wmma::mma_sync(acc[i][j], fah[i], fbh[j], acc[i][j]);
                }
        }
    }
    __syncthreads();

    float* Cs = (float*)sm;
#pragma unroll
    for (int i = 0; i < 4; i++)
#pragma unroll
        for (int j = 0; j < 4; j++)
            wmma::store_matrix_sync(Cs + (wm * 64 + i * 16) * 132 + wn * 64 + j * 16,
                                    acc[i][j], 132, wmma::mem_row_major);
    __syncthreads();
    {
        int c = tid;
        int gn = n0 + c;
        float bb = (bias && gn < validN) ? bias[gn] : 0.f;
#pragma unroll 8
        for (int r = 0; r < 128; r++) {
            float v = Cs[r * 132 + c] + bb;
            if (act) v = (v > 0.f) ? v : expm1f(v);
            size_t o = (size_t)(m0 + r) * ldc + gn;
            if (Cf) Cf[o] = v;
            if (oH) { __nv_bfloat16 h, l2; splitbf(v, h, l2); oH[o] = h; oL[o] = l2; }
        }
    }
}

// ---------------- batched bilinear NT (r12 config restored) ----------------
__global__ void __launch_bounds__(128, 2)
bil_nt_bf16x3(const __nv_bfloat16* __restrict__ t1h, const __nv_bfloat16* __restrict__ t1l,
              const __nv_bfloat16* __restrict__ dah, const __nv_bfloat16* __restrict__ dal,
              const float* __restrict__ bilb, int kidx, float* __restrict__ Cout) {
    extern __shared__ __nv_bfloat16 sm[];
    int tid = threadIdx.x, warp = tid >> 5;
    int wm = warp & 1, wn = warp >> 1;
    int bz = blockIdx.z;
    int i0 = blockIdx.y << 7, j0 = blockIdx.x << 7;
    size_t arow = (size_t)bz * SPc + i0;
    size_t brow = (size_t)bz * SPc + j0;

    wmma::fragment<wmma::accumulator, 16, 16, 16, float> acc[4][4];
#pragma unroll
    for (int i = 0; i < 4; i++)
#pragma unroll
        for (int j = 0; j < 4; j++) wmma::fill_fragment(acc[i][j], 0.f);

    auto load_stage = [&](int st, int k0) {
        __nv_bfloat16* a0 = sm + st * BSTG;
        __nv_bfloat16* a1 = a0 + BPLN;
        __nv_bfloat16* b0 = a1 + BPLN;
        __nv_bfloat16* b1 = b0 + BPLN;
#pragma unroll
        for (int l = 0; l < 4; l++) {
            int id = tid + l * 128;
            int r = id >> 2, c = (id & 3) * 8;
            cp16(a0 + r * 40 + c, t1h + (arow + r) * ARCP + k0 + c);
            cp16(a1 + r * 40 + c, t1l + (arow + r) * ARCP + k0 + c);
            cp16(b0 + r * 40 + c, dah + (brow + r) * ARCP + k0 + c);
            cp16(b1 + r * 40 + c, dal + (brow + r) * ARCP + k0 + c);
        }
        asm volatile("cp.async.commit_group;");
    };

    const int nk = ARCP >> 5;
    load_stage(0, 0);
    load_stage(1, 32);

    for (int kt = 0; kt < nk; kt++) {
        if (kt + 1 < nk) asm volatile("cp.async.wait_group 1;");
        else             asm volatile("cp.async.wait_group 0;");
        __syncthreads();
        int st = kt & 1;
        const __nv_bfloat16* a0 = sm + st * BSTG;
        const __nv_bfloat16* a1 = a0 + BPLN;
        const __nv_bfloat16* b0 = a1 + BPLN;
        const __nv_bfloat16* b1 = b0 + BPLN;
#pragma unroll
        for (int ks = 0; ks < 2; ks++) {
            wmma::fragment<wmma::matrix_a, 16, 16, 16, __nv_bfloat16, wmma::row_major> fah[4], fal[4];
            wmma::fragment<wmma::matrix_b, 16, 16, 16, __nv_bfloat16, wmma::col_major> fbh[4], fbl[4];
#pragma unroll
            for (int i = 0; i < 4; i++) {
                wmma::load_matrix_sync(fah[i], a0 + (wm * 64 + i * 16) * 40 + ks * 16, 40);
                wmma::load_matrix_sync(fal[i], a1 + (wm * 64 + i * 16) * 40 + ks * 16, 40);
            }
#pragma unroll
            for (int j = 0; j < 4; j++) {
                wmma::load_matrix_sync(fbh[j], b0 + (wn * 64 + j * 16) * 40 + ks * 16, 40);
                wmma::load_matrix_sync(fbl[j], b1 + (wn * 64 + j * 16) * 40 + ks * 16, 40);
            }
#pragma unroll
            for (int i = 0; i < 4; i++)
#pragma unroll
                for (int j = 0; j < 4; j++) {
                    wmma::mma_sync(acc[i][j], fal[i], fbh[j], acc[i][j]);
                    wmma::mma_sync(acc[i][j], fah[i], fbl[j], acc[i][j]);
                    wmma::mma_sync(acc[i][j], fah[i], fbh[j], acc[i][j]);
                }
        }
        __syncthreads();
        if (kt + 2 < nk) load_stage(st, (kt + 2) << 5);
    }

    float* Cs = (float*)sm;
    __syncthreads();
#pragma unroll
    for (int i = 0; i < 4; i++)
#pragma unroll
        for (int j = 0; j < 4; j++)
            wmma::store_matrix_sync(Cs + (wm * 64 + i * 16) * 132 + wn * 64 + j * 16,
                                    acc[i][j], 132, wmma::mem_row_major);
    __syncthreads();
    {
        int c = tid;
        int oj = j0 + c;
        float bb = bilb[kidx];
        for (int r = 0; r < 128; r++) {
            int oi = i0 + r;
            size_t brow2 = ((size_t)bz * SPc + oi) * ARCP + ARCc;
            float rowb = __bfloat162float(t1h[brow2]) + __bfloat162float(t1l[brow2]);
            Cout[((size_t)bz * SPc + oi) * SPc + oj] = Cs[r * 132 + c] + rowb + bb;
        }
    }
}

// edge: lg[b, i, 256] and lg[b, 256, j]
__global__ void bil_edge(const __nv_bfloat16* __restrict__ t1h, const __nv_bfloat16* __restrict__ t1l,
                         const __nv_bfloat16* __restrict__ dah, const __nv_bfloat16* __restrict__ dal,
                         const float* __restrict__ bilb, int kidx, float* __restrict__ Cout) {
    int wg = blockIdx.x * 8 + (threadIdx.x >> 5);
    int lane = threadIdx.x & 31;
    int total = Bb * 2 * SPc;
    if (wg >= total) return;
    int b = wg / (2 * SPc);
    int d = wg % (2 * SPc);
    int i = (d < SPc) ? d : 256;
    int j = (d < SPc) ? 256 : (d - SPc);
    const __nv_bfloat16* th = t1h + ((size_t)b * SPc + i) * ARCP;
    const __nv_bfloat16* tl = t1l + ((size_t)b * SPc + i) * ARCP;
    const __nv_bfloat16* dh = dah + ((size_t)b * SPc + j) * ARCP;
    const __nv_bfloat16* dl = dal + ((size_t)b * SPc + j) * ARCP;
    float s = 0.f;
#pragma unroll
    for (int t = 0; t < 16; t++) {
        int c = lane + 32 * t;
        float av = __bfloat162float(th[c]) + __bfloat162float(tl[c]);
        float bv = __bfloat162float(dh[c]) + __bfloat162float(dl[c]);
        s += av * bv;
    }
#pragma unroll
    for (int off = 16; off > 0; off >>= 1) s += __shfl_xor_sync(0xffffffffu, s, off);
    if (lane == 0) {
        float rowb = __bfloat162float(th[ARCc]) + __bfloat162float(tl[ARCc]);
        Cout[((size_t)b * SPc + i) * SPc + j] = s + rowb + bilb[kidx];
    }
}

// ---------------- fused softmax + top-8 + dinv ----------------
__global__ void smax_topk(const float* __restrict__ lg) {
    int row = blockIdx.x * 8 + (threadIdx.x >> 5);
    int lane = threadIdx.x & 31;
    if (row >= NROWS) return;
    const float* p = lg + (size_t)row * SPc;
    float v[9];
    float mx = -INFINITY;
#pragma unroll
    for (int t = 0; t < 9; t++) {
        int c = lane + 32 * t;
        v[t] = (c < SPc) ? p[c] : -INFINITY;
        mx = fmaxf(mx, v[t]);
    }
#pragma unroll
    for (int off = 16; off > 0; off >>= 1) mx = fmaxf(mx, __shfl_xor_sync(0xffffffffu, mx, off));
    float s = 0.f;
#pragma unroll
    for (int t = 0; t < 9; t++) {
        int c = lane + 32 * t;
        if (c < SPc) { v[t] = expf(v[t] - mx); s += v[t]; } else v[t] = -INFINITY;
    }
#pragma unroll
    for (int off = 16; off > 0; off >>= 1) s += __shfl_xor_sync(0xffffffffu, s, off);
    float inv = 1.f / s;
#pragma unroll
    for (int t = 0; t < 9; t++) {
        int c = lane + 32 * t;
        if (c < SPc) v[t] *= inv;
    }
    float acc8 = 0.f;
    for (int it = 0; it < TOPKc; it++) {
        float bv = -INFINITY; int bi = 0x7fffffff;
#pragma unroll
        for (int t = 0; t < 9; t++) {
            int c = lane + 32 * t;
            if (v[t] > bv || (v[t] == bv && c < bi)) { bv = v[t]; bi = c; }
        }
#pragma unroll
        for (int off = 16; off > 0; off >>= 1) {
            float ov = __shfl_down_sync(0xffffffffu, bv, off);
            int oi   = __shfl_down_sync(0xffffffffu, bi, off);
            if (ov > bv || (ov == bv && oi < bi)) { bv = ov; bi = oi; }
        }
        bv = __shfl_sync(0xffffffffu, bv, 0);
        bi = __shfl_sync(0xffffffffu, bi, 0);
        if (lane == 0) { g_vals[(size_t)row * TOPKc + it] = bv; g_idx[(size_t)row * TOPKc + it] = bi; }
        acc8 += bv;
        if (lane == (bi & 31)) v[bi >> 5] = -INFINITY;
    }
    if (lane == 0) g_dinv[row] = rsqrtf(1.f + acc8);
}

// ---------------- GCN aggregate + ELU + split (float4) ----------------
__global__ void gcn_agg_split(const float* __restrict__ xw, const float* __restrict__ bias,
                              __nv_bfloat16* __restrict__ outh, __nv_bfloat16* __restrict__ outl,
                              int Fp, int Fv, int act) {
    int gid = blockIdx.x;
    int i = gid % NROWS;
    int stream = gid / NROWS;
    int b = i / SPc;
    __shared__ float cf[TOPKc];
    __shared__ int   ss[TOPKc];
    float di = g_dinv[i];
    if (threadIdx.x < TOPKc) {
        int k = threadIdx.x;
        int srow = b * SPc + g_idx[(size_t)i * TOPKc + k];
        ss[k] = stream * NROWS + srow;
        cf[k] = di * g_vals[(size_t)i * TOPKc + k] * g_dinv[srow];
    }
    __syncthreads();
    float selfc = di * di;
    int nf4 = Fp >> 2;
    const float4* x4 = (const float4*)xw;
    for (int f = threadIdx.x; f < nf4; f += blockDim.x) {
        float4 a = x4[(size_t)gid * nf4 + f];
        float4 acc = make_float4(selfc * a.x, selfc * a.y, selfc * a.z, selfc * a.w);
#pragma unroll
        for (int k = 0; k < TOPKc; k++) {
            float4 sv = x4[(size_t)ss[k] * nf4 + f];
            float c = cf[k];
            acc.x += c * sv.x; acc.y += c * sv.y; acc.z += c * sv.z; acc.w += c * sv.w;
        }
        if (f * 4 < Fv) {
            float4 bv = ((const float4*)bias)[f];
            acc.x += bv.x; acc.y += bv.y; acc.z += bv.z; acc.w += bv.w;
        }
        if (act) {
            acc.x = (acc.x > 0.f) ? acc.x : expm1f(acc.x);
            acc.y = (acc.y > 0.f) ? acc.y : expm1f(acc.y);
            acc.z = (acc.z > 0.f) ? acc.z : expm1f(acc.z);
            acc.w = (acc.w > 0.f) ? acc.w : expm1f(acc.w);
        }
        size_t o = (size_t)gid * Fp + f * 4;
        __nv_bfloat16 h0, l0, h1, l1, h2, l2, h3, l3;
        splitbf(acc.x, h0, l0); splitbf(acc.y, h1, l1);
        splitbf(acc.z, h2, l2); splitbf(acc.w, h3, l3);
        outh[o] = h0; outh[o + 1] = h1; outh[o + 2] = h2; outh[o + 3] = h3;
        outl[o] = l0; outl[o + 1] = l1; outl[o + 2] = l2; outl[o + 3] = l3;
    }
}

// strided copy reconstructing fp32 from hi+lo planes
__global__ void copy_hl(const __nv_bfloat16* __restrict__ h, const __nv_bfloat16* __restrict__ l,
                        float* __restrict__ dst, int ld, int valid, int rows) {
    long i = (long)blockIdx.x * blockDim.x + threadIdx.x;
    long total = (long)rows * valid;
    if (i >= total) return;
    int n = (int)(i / valid), f = (int)(i % valid);
    size_t o = (size_t)n * ld + f;
    dst[i] = __bfloat162float(h[o]) + __bfloat162float(l[o]);
}

// ---------------- host ----------------
template <typename T>
static T* sym(const void* s) { void* p; cudaGetSymbolAddress(&p, s); return (T*)p; }

static void run_gemm(cudaStream_t st, const __nv_bfloat16* Ah, const __nv_bfloat16* Al, int lda,
                     const __nv_bfloat16* Bh, const __nv_bfloat16* Bl, int Npad,
                     float* Cf, __nv_bfloat16* oH, __nv_bfloat16* oL,
                     const float* bias, int validN, int act,
                     int M, int Kpad) {
    dim3 grid(Npad >> 7, M >> 7);
    gemm_bf16x3<<<grid, 128, GSMEM, st>>>(Ah, Al, lda, Bh, Bl, Npad, Cf, Npad, oH, oL, bias, validN, act, Kpad);
}

extern "C" void kernel_launch(void* const* d_in, const int* in_sizes, int n_in,
                              void* d_out, int out_size) {
    const float* inputs = (const float*)d_in[0];
    const float* sent   = (const float*)d_in[5];
    const float* W_ha = (const float*)d_in[6];  const float* b_ha = (const float*)d_in[7];
    const float* W_da = (const float*)d_in[8];  const float* b_da = (const float*)d_in[9];
    const float* W_ht = (const float*)d_in[10]; const float* b_ht = (const float*)d_in[11];
    const float* W_dt = (const float*)d_in[12]; const float* b_dt = (const float*)d_in[13];
    const float* bilW = (const float*)d_in[14]; const float* bilb = (const float*)d_in[15];
    const float* c1aW = (const float*)d_in[16]; const float* c1ab = (const float*)d_in[17];
    const float* c2aW = (const float*)d_in[18]; const float* c2ab = (const float*)d_in[19];
    const float* c1rW = (const float*)d_in[20]; const float* c1rb = (const float*)d_in[21];
    const float* c2rW = (const float*)d_in[22]; const float* c2rb = (const float*)d_in[23];
    float* out = (float*)d_out;

    static cudaStream_t s2 = nullptr;
    static cudaEvent_t ev0, evT0, evT1, evJ;
    if (!s2) {
        cudaStreamCreateWithFlags(&s2, cudaStreamNonBlocking);
        cudaEventCreateWithFlags(&ev0, cudaEventDisableTiming);
        cudaEventCreateWithFlags(&evT0, cudaEventDisableTiming);
        cudaEventCreateWithFlags(&evT1, cudaEventDisableTiming);
        cudaEventCreateWithFlags(&evJ, cudaEventDisableTiming);
    }
    cudaStream_t ms = 0;

    cudaFuncSetAttribute(gemm_bf16x3, cudaFuncAttributeMaxDynamicSharedMemorySize, GSMEM);
    cudaFuncSetAttribute(bil_nt_bf16x3, cudaFuncAttributeMaxDynamicSharedMemorySize, BILSMEM);

    float* lg   = sym<float>(g_lg);
    float* xw   = sym<float>(g_xw);
    float* xwt  = sym<float>(g_xwt);
    __nv_bfloat16 *xH = sym<__nv_bfloat16>(g_xH), *xL = sym<__nv_bfloat16>(g_xL);
    __nv_bfloat16 *arcH = sym<__nv_bfloat16>(g_arcH), *arcL = sym<__nv_bfloat16>(g_arcL);
    __nv_bfloat16 *tagH = sym<__nv_bfloat16>(g_tagH), *tagL = sym<__nv_bfloat16>(g_tagL);
    __nv_bfloat16 *t1H = sym<__nv_bfloat16>(g_t1H), *t1L = sym<__nv_bfloat16>(g_t1L);
    __nv_bfloat16 *hH = sym<__nv_bfloat16>(g_hH), *hL = sym<__nv_bfloat16>(g_hL);
    __nv_bfloat16 *thH = sym<__nv_bfloat16>(g_thH), *thL = sym<__nv_bfloat16>(g_thL);
    __nv_bfloat16 *whaH = sym<__nv_bfloat16>(g_whaH), *whaL = sym<__nv_bfloat16>(g_whaL);
    __nv_bfloat16 *wdaH = sym<__nv_bfloat16>(g_wdaH), *wdaL = sym<__nv_bfloat16>(g_wdaL);
    __nv_bfloat16 *whtH = sym<__nv_bfloat16>(g_whtH), *whtL = sym<__nv_bfloat16>(g_whtL);
    __nv_bfloat16 *wdtH = sym<__nv_bfloat16>(g_wdtH), *wdtL = sym<__nv_bfloat16>(g_wdtL);
    __nv_bfloat16 *bilH = sym<__nv_bfloat16>(g_bilH), *bilL = sym<__nv_bfloat16>(g_bilL);
    __nv_bfloat16 *c1aH = sym<__nv_bfloat16>(g_c1aH), *c1aL = sym<__nv_bfloat16>(g_c1aL);
    __nv_bfloat16 *c2aH = sym<__nv_bfloat16>(g_c2aH), *c2aL = sym<__nv_bfloat16>(g_c2aL);
    __nv_bfloat16 *c1rH = sym<__nv_bfloat16>(g_c1rH), *c1rL = sym<__nv_bfloat16>(g_c1rL);
    __nv_bfloat16 *c2rH = sym<__nv_bfloat16>(g_c2rH), *c2rL = sym<__nv_bfloat16>(g_c2rL);

    __nv_bfloat16 *haH = arcH, *haL = arcL;
    __nv_bfloat16 *daH = arcH + (size_t)NROWS * ARCP, *daL = arcL + (size_t)NROWS * ARCP;
    __nv_bfloat16 *htH = tagH, *htL = tagL;
    __nv_bfloat16 *dtH = tagH + (size_t)NROWS * TAGP, *dtL = tagL + (size_t)NROWS * TAGP;

    // --- fused weight pack ---
    {
        PTab t;
        long base = 0;
        auto add = [&](int q, const float* src, __nv_bfloat16* hi, __nv_bfloat16* lo,
                       int Wr, int Wc, int ldw, int Kp, int Np) {
            t.j[q] = {src, hi, lo, Wr, Wc, ldw, Np, base, base + (long)Kp * Np};
            base += (long)Kp * Np;
        };
        add(0, W_ha, whaH, whaL, 768, 500, 500, 768, 512);
        add(1, W_da, wdaH, wdaL, 768, 500, 500, 768, 512);
        add(2, W_ht, whtH, whtL, 768, 100, 100, 768, 128);
        add(3, W_dt, wdtH, wdtL, 768, 100, 100, 768, 128);
        for (int k = 0; k < 3; k++)
            add(4 + k, bilW + (size_t)k * 501 * 501, bilH + (size_t)k * 512 * 512,
                bilL + (size_t)k * 512 * 512, 500, 501, 501, 512, 512);
        add(7, c1aW, c1aH, c1aL, 500, 500, 500, 512, 512);
        add(8, c2aW, c2aH, c2aL, 500, 500, 500, 512, 512);
        add(9, c1rW, c1rH, c1rL, 100, 100, 100, 128, 128);
        add(10, c2rW, c2rH, c2rL, 100, 100, 100, 128, 128);
        pack_all<<<(unsigned)((base + 255) / 256), 256, 0, ms>>>(t, base);
    }

    // --- x ---
    build_x_split<<<NROWS, 256, 0, ms>>>(inputs, sent, xH, xL);
    cudaEventRecord(ev0, ms);
    cudaStreamWaitEvent(s2, ev0, 0);

    run_gemm(ms, xH, xL, Dd, whaH, whaL, ARCP, nullptr, haH, haL, b_ha, ARCc, 1, NROWS, Dd);
    run_gemm(ms, xH, xL, Dd, wdaH, wdaL, ARCP, nullptr, daH, daL, b_da, ARCc, 1, NROWS, Dd);
    run_gemm(s2, xH, xL, Dd, whtH, whtL, TAGP, nullptr, htH, htL, b_ht, TAGc, 1, NROWS, Dd);
    run_gemm(s2, xH, xL, Dd, wdtH, wdtL, TAGP, nullptr, dtH, dtL, b_dt, TAGc, 1, NROWS, Dd);

    dim3 bilgrid(2, 2, Bb);
    int edgegrid = (Bb * 2 * SPc + 7) / 8;
    int smgrid = (NROWS + 7) / 8;
    cudaEvent_t evT[2] = {evT0, evT1};

    for (int k = 0; k < 2; k++) {
        run_gemm(ms, haH, haL, ARCP, bilH + (size_t)k * 512 * 512, bilL + (size_t)k * 512 * 512, ARCP,
                 nullptr, t1H, t1L, bilW + (size_t)k * 501 * 501 + (size_t)500 * 501, 501, 0, NROWS, ARCP);
        bil_nt_bf16x3<<<bilgrid, 128, BILSMEM, ms>>>(t1H, t1L, daH, daL, bilb, k, lg);
        bil_edge<<<edgegrid, 256, 0, ms>>>(t1H, t1L, daH, daL, bilb, k, lg);
        smax_topk<<<smgrid, 256, 0, ms>>>(lg);
        cudaEventRecord(evT[k], ms);
        cudaStreamWaitEvent(s2, evT[k], 0);

        // arc chain (main)
        run_gemm(ms, arcH, arcL, ARCP, c1aH, c1aL, ARCP, xw, nullptr, nullptr, nullptr, 0, 0, 2 * NROWS, ARCP);
        gcn_agg_split<<<2 * NROWS, 128, 0, ms>>>(xw, c1ab, hH, hL, ARCP, ARCc, 1);
        run_gemm(ms, hH, hL, ARCP, c2aH, c2aL, ARCP, xw, nullptr, nullptr, nullptr, 0, 0, 2 * NROWS, ARCP);
        gcn_agg_split<<<2 * NROWS, 128, 0, ms>>>(xw, c2ab, arcH, arcL, ARCP, ARCc, 0);
        // tag chain (s2)
        run_gemm(s2, tagH, tagL, TAGP, c1rH, c1rL, TAGP, xwt, nullptr, nullptr, nullptr, 0, 0, 2 * NROWS, TAGP);
        gcn_agg_split<<<2 * NROWS, 128, 0, s2>>>(xwt, c1rb, thH, thL, TAGP, TAGc, 1);
        run_gemm(s2, thH, thL, TAGP, c2rH, c2rL, TAGP, xwt, nullptr, nullptr, nullptr, 0, 0, 2 * NROWS, TAGP);
        gcn_agg_split<<<2 * NROWS, 128, 0, s2>>>(xwt, c2rb, tagH, tagL, TAGP, TAGc, 0);
    }

    // final bilinear -> d_out (main) ; tag output copies (s2)
    long arcN = (long)Bb * SPc * SPc;
    long tagN = (long)NROWS * TAGc;
    run_gemm(ms, haH, haL, ARCP, bilH + (size_t)2 * 512 * 512, bilL + (size_t)2 * 512 * 512, ARCP,
             nullptr, t1H, t1L, bilW + (size_t)2 * 501 * 501 + (size_t)500 * 501, 501, 0, NROWS, ARCP);
    bil_nt_bf16x3<<<bilgrid, 128, BILSMEM, ms>>>(t1H, t1L, daH, daL, bilb, 2, out);
    bil_edge<<<edgegrid, 256, 0, ms>>>(t1H, t1L, daH, daL, bilb, 2, out);

    copy_hl<<<(unsigned)((tagN + 255) / 256), 256, 0, s2>>>(htH, htL, out + arcN, TAGP, TAGc, NROWS);
    copy_hl<<<(unsigned)((tagN + 255) / 256), 256, 0, s2>>>(dtH, dtL, out + arcN + tagN, TAGP, TAGc, NROWS);

    cudaEventRecord(evJ, s2);
    cudaStreamWaitEvent(ms, evJ, 0);
}

// round 16
// speedup vs baseline: 2.1500x; 1.0311x over previous
#include <cuda_runtime.h>
#include <cuda_bf16.h>
#include <math.h>
#include <mma.h>
#include <stdint.h>
using namespace nvcuda;

// ---------------- problem constants ----------------
static const int Bb   = 128;
static const int Ss   = 256;
static const int Dd   = 768;
static const int SPc  = 257;
static const int NROWS = Bb * SPc;           // 32896
static const int ARCc = 500;
static const int TAGc = 100;
static const int TOPKc = 8;
static const int ARCP = 512;
static const int TAGP = 128;
static const int PADR = 128;

// main GEMM tiling: 128x128 CTA tile, 4 warps (64x64), k-chunk 32, 3-stage
static const int ASTR = 40;
static const int BSTR = 136;
static const int APL  = 128 * ASTR;
static const int BPL  = 32 * BSTR;
static const int STG  = 2 * APL + 2 * BPL;
static const int NST  = 3;
static const int GSMEM = NST * STG * 2;       // 113664 B (2 CTAs/SM)

// bil tiling: 128x128 tile, 4 warps (64x64), k-chunk 32, 2-stage
static const int BPLN = 128 * 40;
static const int BSTG = 4 * BPLN;
static const int BILSMEM = 2 * BSTG * 2;      // 81920 B

// ---------------- fp32 scratch ----------------
__device__ float g_lg  [Bb * SPc * SPc];
__device__ float g_xw  [2 * NROWS * ARCP];
__device__ float g_xwt [2 * NROWS * TAGP];
__device__ float g_vals[NROWS * TOPKc];
__device__ int   g_idx [NROWS * TOPKc];
__device__ float g_dinv[NROWS];

// ---------------- bf16 hi/lo planes ----------------
__device__ __align__(16) __nv_bfloat16 g_xH[NROWS * Dd],  g_xL[NROWS * Dd];
__device__ __align__(16) __nv_bfloat16 g_arcH[(2 * NROWS + PADR) * ARCP], g_arcL[(2 * NROWS + PADR) * ARCP];
__device__ __align__(16) __nv_bfloat16 g_tagH[2 * NROWS * TAGP], g_tagL[2 * NROWS * TAGP];
__device__ __align__(16) __nv_bfloat16 g_t1H[(NROWS + PADR) * ARCP], g_t1L[(NROWS + PADR) * ARCP];
__device__ __align__(16) __nv_bfloat16 g_hH[2 * NROWS * ARCP], g_hL[2 * NROWS * ARCP];
__device__ __align__(16) __nv_bfloat16 g_thH[2 * NROWS * TAGP], g_thL[2 * NROWS * TAGP];
// weights [Kpad, Npad] row-major, padded, split
__device__ __align__(16) __nv_bfloat16 g_whaH[768 * 512], g_whaL[768 * 512];
__device__ __align__(16) __nv_bfloat16 g_wdaH[768 * 512], g_wdaL[768 * 512];
__device__ __align__(16) __nv_bfloat16 g_whtH[768 * 128], g_whtL[768 * 128];
__device__ __align__(16) __nv_bfloat16 g_wdtH[768 * 128], g_wdtL[768 * 128];
__device__ __align__(16) __nv_bfloat16 g_bilH[3 * 512 * 512], g_bilL[3 * 512 * 512];
__device__ __align__(16) __nv_bfloat16 g_c1aH[512 * 512], g_c1aL[512 * 512];
__device__ __align__(16) __nv_bfloat16 g_c2aH[512 * 512], g_c2aL[512 * 512];
__device__ __align__(16) __nv_bfloat16 g_c1rH[128 * 128], g_c1rL[128 * 128];
__device__ __align__(16) __nv_bfloat16 g_c2rH[128 * 128], g_c2rL[128 * 128];

__device__ __forceinline__ void splitbf(float v, __nv_bfloat16& h, __nv_bfloat16& l) {
    h = __float2bfloat16(v);
    l = __float2bfloat16(v - __bfloat162float(h));
}
__device__ __forceinline__ void cp16(void* dst, const void* src) {
    unsigned d = (unsigned)__cvta_generic_to_shared(dst);
    asm volatile("cp.async.cg.shared.global [%0], [%1], 16;" :: "r"(d), "l"(src));
}

// ---------------- fused weight pack ----------------
struct PJob {
    const float* src; __nv_bfloat16* hi; __nv_bfloat16* lo;
    int Wr, Wc, ldw, Np; long base, end;
};
struct PTab { PJob j[11]; };

__global__ void pack_all(PTab t, long total) {
    long i = (long)blockIdx.x * blockDim.x + threadIdx.x;
    if (i >= total) return;
#pragma unroll
    for (int q = 0; q < 11; q++) {
        if (i < t.j[q].end) {
            long loc = i - t.j[q].base;
            int r = (int)(loc / t.j[q].Np), c = (int)(loc % t.j[q].Np);
            float v = (r < t.j[q].Wr && c < t.j[q].Wc) ? t.j[q].src[(size_t)r * t.j[q].ldw + c] : 0.f;
            splitbf(v, t.j[q].hi[loc], t.j[q].lo[loc]);
            return;
        }
    }
}

__global__ void build_x_split(const float* __restrict__ inp, const float* __restrict__ sent,
                              __nv_bfloat16* __restrict__ xh, __nv_bfloat16* __restrict__ xl) {
    int n = blockIdx.x;
    int b = n / SPc, r = n % SPc;
    const float* src = (r == 0) ? sent : (inp + ((size_t)b * Ss + (r - 1)) * Dd);
    for (int f = threadIdx.x; f < Dd; f += blockDim.x)
        splitbf(src[f], xh[(size_t)n * Dd + f], xl[(size_t)n * Dd + f]);
}

// ---------------- main GEMM (r12 exact: 4 warps 64x64, 2 CTAs/SM, id-based addressing) ----
__global__ void __launch_bounds__(128, 2)
gemm_bf16x3(const __nv_bfloat16* __restrict__ Ah, const __nv_bfloat16* __restrict__ Al, int lda,
            const __nv_bfloat16* __restrict__ Bh, const __nv_bfloat16* __restrict__ Bl, int ldb,
            float* __restrict__ Cf, int ldc,
            __nv_bfloat16* __restrict__ oH, __nv_bfloat16* __restrict__ oL,
            const float* __restrict__ bias, int validN, int act, int Kpad) {
    extern __shared__ __nv_bfloat16 sm[];
    int tid = threadIdx.x, warp = tid >> 5;
    int wm = warp & 1, wn = warp >> 1;
    int m0 = blockIdx.y << 7, n0 = blockIdx.x << 7;

    wmma::fragment<wmma::accumulator, 16, 16, 16, float> acc[4][4];
#pragma unroll
    for (int i = 0; i < 4; i++)
#pragma unroll
        for (int j = 0; j < 4; j++) wmma::fill_fragment(acc[i][j], 0.f);

    int nk = Kpad >> 5;

    auto load_stage = [&](int st, int k0) {
        __nv_bfloat16* a0 = sm + st * STG;
        __nv_bfloat16* a1 = a0 + APL;
        __nv_bfloat16* b0 = a1 + APL;
        __nv_bfloat16* b1 = b0 + BPL;
#pragma unroll
        for (int l = 0; l < 4; l++) {
            int id = tid + l * 128;
            int r = id >> 2, c = (id & 3) * 8;
            cp16(a0 + r * ASTR + c, Ah + (size_t)(m0 + r) * lda + k0 + c);
            cp16(a1 + r * ASTR + c, Al + (size_t)(m0 + r) * lda + k0 + c);
        }
#pragma unroll
        for (int l = 0; l < 4; l++) {
            int id = tid + l * 128;
            int r = id >> 4, c = (id & 15) * 8;
            cp16(b0 + r * BSTR + c, Bh + (size_t)(k0 + r) * ldb + n0 + c);
            cp16(b1 + r * BSTR + c, Bl + (size_t)(k0 + r) * ldb + n0 + c);
        }
        asm volatile("cp.async.commit_group;");
    };

    load_stage(0, 0);
    load_stage(1, 32);

    for (int kt = 0; kt < nk; kt++) {
        if (kt + 1 < nk) asm volatile("cp.async.wait_group 1;");
        else             asm volatile("cp.async.wait_group 0;");
        __syncthreads();
        if (kt + 2 < nk) load_stage((kt + 2) % NST, (kt + 2) << 5);

        int st = kt % NST;
        const __nv_bfloat16* a0 = sm + st * STG;
        const __nv_bfloat16* a1 = a0 + APL;
        const __nv_bfloat16* b0 = a1 + APL;
        const __nv_bfloat16* b1 = b0 + BPL;
#pragma unroll
        for (int ks = 0; ks < 2; ks++) {
            wmma::fragment<wmma::matrix_a, 16, 16, 16, __nv_bfloat16, wmma::row_major> fah[4], fal[4];
            wmma::fragment<wmma::matrix_b, 16, 16, 16, __nv_bfloat16, wmma::row_major> fbh[4], fbl[4];
#pragma unroll
            for (int i = 0; i < 4; i++) {
                wmma::load_matrix_sync(fah[i], a0 + (wm * 64 + i * 16) * ASTR + ks * 16, ASTR);
                wmma::load_matrix_sync(fal[i], a1 + (wm * 64 + i * 16) * ASTR + ks * 16, ASTR);
            }
#pragma unroll
            for (int j = 0; j < 4; j++) {
                wmma::load_matrix_sync(fbh[j], b0 + (ks * 16) * BSTR + wn * 64 + j * 16, BSTR);
                wmma::load_matrix_sync(fbl[j], b1 + (ks * 16) * BSTR + wn * 64 + j * 16, BSTR);
            }
#pragma unroll
            for (int i = 0; i < 4; i++)
#pragma unroll
                for (int j = 0; j < 4; j++) {
                    wmma::mma_sync(acc[i][j], fal[i], fbh[j], acc[i][j]);
                    wmma::mma_sync(acc[i][j], fah[i], fbl[j], acc[i][j]);
                    wmma::mma_sync(acc[i][j], fah[i], fbh[j], acc[i][j]);
                }
        }
    }
    __syncthreads();

    float* Cs = (float*)sm;
#pragma unroll
    for (int i = 0; i < 4; i++)
#pragma unroll
        for (int j = 0; j < 4; j++)
            wmma::store_matrix_sync(Cs + (wm * 64 + i * 16) * 132 + wn * 64 + j * 16,
                                    acc[i][j], 132, wmma::mem_row_major);
    __syncthreads();
    {
        int c = tid;
        int gn = n0 + c;
        float bb = (bias && gn < validN) ? bias[gn] : 0.f;
#pragma unroll 8
        for (int r = 0; r < 128; r++) {
            float v = Cs[r * 132 + c] + bb;
            if (act) v = (v > 0.f) ? v : expm1f(v);
            size_t o = (size_t)(m0 + r) * ldc + gn;
            if (Cf) Cf[o] = v;
            if (oH) { __nv_bfloat16 h, l2; splitbf(v, h, l2); oH[o] = h; oL[o] = l2; }
        }
    }
}

// ---------------- batched bilinear NT (full tiles; edges separate) ----------------
__global__ void __launch_bounds__(128, 2)
bil_nt_bf16x3(const __nv_bfloat16* __restrict__ t1h, const __nv_bfloat16* __restrict__ t1l,
              const __nv_bfloat16* __restrict__ dah, const __nv_bfloat16* __restrict__ dal,
              const float* __restrict__ bilb, int kidx, float* __restrict__ Cout) {
    extern __shared__ __nv_bfloat16 sm[];
    int tid = threadIdx.x, warp = tid >> 5;
    int wm = warp & 1, wn = warp >> 1;
    int bz = blockIdx.z;
    int i0 = blockIdx.y << 7, j0 = blockIdx.x << 7;
    size_t arow = (size_t)bz * SPc + i0;
    size_t brow = (size_t)bz * SPc + j0;

    wmma::fragment<wmma::accumulator, 16, 16, 16, float> acc[4][4];
#pragma unroll
    for (int i = 0; i < 4; i++)
#pragma unroll
        for (int j = 0; j < 4; j++) wmma::fill_fragment(acc[i][j], 0.f);

    auto load_stage = [&](int st, int k0) {
        __nv_bfloat16* a0 = sm + st * BSTG;
        __nv_bfloat16* a1 = a0 + BPLN;
        __nv_bfloat16* b0 = a1 + BPLN;
        __nv_bfloat16* b1 = b0 + BPLN;
#pragma unroll
        for (int l = 0; l < 4; l++) {
            int id = tid + l * 128;
            int r = id >> 2, c = (id & 3) * 8;
            cp16(a0 + r * 40 + c, t1h + (arow + r) * ARCP + k0 + c);
            cp16(a1 + r * 40 + c, t1l + (arow + r) * ARCP + k0 + c);
            cp16(b0 + r * 40 + c, dah + (brow + r) * ARCP + k0 + c);
            cp16(b1 + r * 40 + c, dal + (brow + r) * ARCP + k0 + c);
        }
        asm volatile("cp.async.commit_group;");
    };

    const int nk = ARCP >> 5;
    load_stage(0, 0);
    load_stage(1, 32);

    for (int kt = 0; kt < nk; kt++) {
        if (kt + 1 < nk) asm volatile("cp.async.wait_group 1;");
        else             asm volatile("cp.async.wait_group 0;");
        __syncthreads();
        int st = kt & 1;
        const __nv_bfloat16* a0 = sm + st * BSTG;
        const __nv_bfloat16* a1 = a0 + BPLN;
        const __nv_bfloat16* b0 = a1 + BPLN;
        const __nv_bfloat16* b1 = b0 + BPLN;
#pragma unroll
        for (int ks = 0; ks < 2; ks++) {
            wmma::fragment<wmma::matrix_a, 16, 16, 16, __nv_bfloat16, wmma::row_major> fah[4], fal[4];
            wmma::fragment<wmma::matrix_b, 16, 16, 16, __nv_bfloat16, wmma::col_major> fbh[4], fbl[4];
#pragma unroll
            for (int i = 0; i < 4; i++) {
                wmma::load_matrix_sync(fah[i], a0 + (wm * 64 + i * 16) * 40 + ks * 16, 40);
                wmma::load_matrix_sync(fal[i], a1 + (wm * 64 + i * 16) * 40 + ks * 16, 40);
            }
#pragma unroll
            for (int j = 0; j < 4; j++) {
                wmma::load_matrix_sync(fbh[j], b0 + (wn * 64 + j * 16) * 40 + ks * 16, 40);
                wmma::load_matrix_sync(fbl[j], b1 + (wn * 64 + j * 16) * 40 + ks * 16, 40);
            }
#pragma unroll
            for (int i = 0; i < 4; i++)
#pragma unroll
                for (int j = 0; j < 4; j++) {
                    wmma::mma_sync(acc[i][j], fal[i], fbh[j], acc[i][j]);
                    wmma::mma_sync(acc[i][j], fah[i], fbl[j], acc[i][j]);
                    wmma::mma_sync(acc[i][j], fah[i], fbh[j], acc[i][j]);
                }
        }
        __syncthreads();
        if (kt + 2 < nk) load_stage(st, (kt + 2) << 5);
    }

    float* Cs = (float*)sm;
    __syncthreads();
#pragma unroll
    for (int i = 0; i < 4; i++)
#pragma unroll
        for (int j = 0; j < 4; j++)
            wmma::store_matrix_sync(Cs + (wm * 64 + i * 16) * 132 + wn * 64 + j * 16,
                                    acc[i][j], 132, wmma::mem_row_major);
    __syncthreads();
    {
        int c = tid;
        int oj = j0 + c;
        float bb = bilb[kidx];
        for (int r = 0; r < 128; r++) {
            int oi = i0 + r;
            size_t brow2 = ((size_t)bz * SPc + oi) * ARCP + ARCc;
            float rowb = __bfloat162float(t1h[brow2]) + __bfloat162float(t1l[brow2]);
            Cout[((size_t)bz * SPc + oi) * SPc + oj] = Cs[r * 132 + c] + rowb + bb;
        }
    }
}

// edge: lg[b, i, 256] and lg[b, 256, j]
__global__ void bil_edge(const __nv_bfloat16* __restrict__ t1h, const __nv_bfloat16* __restrict__ t1l,
                         const __nv_bfloat16* __restrict__ dah, const __nv_bfloat16* __restrict__ dal,
                         const float* __restrict__ bilb, int kidx, float* __restrict__ Cout) {
    int wg = blockIdx.x * 8 + (threadIdx.x >> 5);
    int lane = threadIdx.x & 31;
    int total = Bb * 2 * SPc;
    if (wg >= total) return;
    int b = wg / (2 * SPc);
    int d = wg % (2 * SPc);
    int i = (d < SPc) ? d : 256;
    int j = (d < SPc) ? 256 : (d - SPc);
    const __nv_bfloat16* th = t1h + ((size_t)b * SPc + i) * ARCP;
    const __nv_bfloat16* tl = t1l + ((size_t)b * SPc + i) * ARCP;
    const __nv_bfloat16* dh = dah + ((size_t)b * SPc + j) * ARCP;
    const __nv_bfloat16* dl = dal + ((size_t)b * SPc + j) * ARCP;
    float s = 0.f;
#pragma unroll
    for (int t = 0; t < 16; t++) {
        int c = lane + 32 * t;
        float av = __bfloat162float(th[c]) + __bfloat162float(tl[c]);
        float bv = __bfloat162float(dh[c]) + __bfloat162float(dl[c]);
        s += av * bv;
    }
#pragma unroll
    for (int off = 16; off > 0; off >>= 1) s += __shfl_xor_sync(0xffffffffu, s, off);
    if (lane == 0) {
        float rowb = __bfloat162float(th[ARCc]) + __bfloat162float(tl[ARCc]);
        Cout[((size_t)b * SPc + i) * SPc + j] = s + rowb + bilb[kidx];
    }
}

// ---------------- fused softmax + top-8 + dinv ----------------
__global__ void smax_topk(const float* __restrict__ lg) {
    int row = blockIdx.x * 8 + (threadIdx.x >> 5);
    int lane = threadIdx.x & 31;
    if (row >= NROWS) return;
    const float* p = lg + (size_t)row * SPc;
    float v[9];
    float mx = -INFINITY;
#pragma unroll
    for (int t = 0; t < 9; t++) {
        int c = lane + 32 * t;
        v[t] = (c < SPc) ? p[c] : -INFINITY;
        mx = fmaxf(mx, v[t]);
    }
#pragma unroll
    for (int off = 16; off > 0; off >>= 1) mx = fmaxf(mx, __shfl_xor_sync(0xffffffffu, mx, off));
    float s = 0.f;
#pragma unroll
    for (int t = 0; t < 9; t++) {
        int c = lane + 32 * t;
        if (c < SPc) { v[t] = expf(v[t] - mx); s += v[t]; } else v[t] = -INFINITY;
    }
#pragma unroll
    for (int off = 16; off > 0; off >>= 1) s += __shfl_xor_sync(0xffffffffu, s, off);
    float inv = 1.f / s;
#pragma unroll
    for (int t = 0; t < 9; t++) {
        int c = lane + 32 * t;
        if (c < SPc) v[t] *= inv;
    }
    float acc8 = 0.f;
    for (int it = 0; it < TOPKc; it++) {
        float bv = -INFINITY; int bi = 0x7fffffff;
#pragma unroll
        for (int t = 0; t < 9; t++) {
            int c = lane + 32 * t;
            if (v[t] > bv || (v[t] == bv && c < bi)) { bv = v[t]; bi = c; }
        }
#pragma unroll
        for (int off = 16; off > 0; off >>= 1) {
            float ov = __shfl_down_sync(0xffffffffu, bv, off);
            int oi   = __shfl_down_sync(0xffffffffu, bi, off);
            if (ov > bv || (ov == bv && oi < bi)) { bv = ov; bi = oi; }
        }
        bv = __shfl_sync(0xffffffffu, bv, 0);
        bi = __shfl_sync(0xffffffffu, bi, 0);
        if (lane == 0) { g_vals[(size_t)row * TOPKc + it] = bv; g_idx[(size_t)row * TOPKc + it] = bi; }
        acc8 += bv;
        if (lane == (bi & 31)) v[bi >> 5] = -INFINITY;
    }
    if (lane == 0) g_dinv[row] = rsqrtf(1.f + acc8);
}

// ---------------- GCN aggregate + ELU + split (float4) ----------------
__global__ void gcn_agg_split(const float* __restrict__ xw, const float* __restrict__ bias,
                              __nv_bfloat16* __restrict__ outh, __nv_bfloat16* __restrict__ outl,
                              int Fp, int Fv, int act) {
    int gid = blockIdx.x;
    int i = gid % NROWS;
    int stream = gid / NROWS;
    int b = i / SPc;
    __shared__ float cf[TOPKc];
    __shared__ int   ss[TOPKc];
    float di = g_dinv[i];
    if (threadIdx.x < TOPKc) {
        int k = threadIdx.x;
        int srow = b * SPc + g_idx[(size_t)i * TOPKc + k];
        ss[k] = stream * NROWS + srow;
        cf[k] = di * g_vals[(size_t)i * TOPKc + k] * g_dinv[srow];
    }
    __syncthreads();
    float selfc = di * di;
    int nf4 = Fp >> 2;
    const float4* x4 = (const float4*)xw;
    for (int f = threadIdx.x; f < nf4; f += blockDim.x) {
        float4 a = x4[(size_t)gid * nf4 + f];
        float4 acc = make_float4(selfc * a.x, selfc * a.y, selfc * a.z, selfc * a.w);
#pragma unroll
        for (int k = 0; k < TOPKc; k++) {
            float4 sv = x4[(size_t)ss[k] * nf4 + f];
            float c = cf[k];
            acc.x += c * sv.x; acc.y += c * sv.y; acc.z += c * sv.z; acc.w += c * sv.w;
        }
        if (f * 4 < Fv) {
            float4 bv = ((const float4*)bias)[f];
            acc.x += bv.x; acc.y += bv.y; acc.z += bv.z; acc.w += bv.w;
        }
        if (act) {
            acc.x = (acc.x > 0.f) ? acc.x : expm1f(acc.x);
            acc.y = (acc.y > 0.f) ? acc.y : expm1f(acc.y);
            acc.z = (acc.z > 0.f) ? acc.z : expm1f(acc.z);
            acc.w = (acc.w > 0.f) ? acc.w : expm1f(acc.w);
        }
        size_t o = (size_t)gid * Fp + f * 4;
        __nv_bfloat16 h0, l0, h1, l1, h2, l2, h3, l3;
        splitbf(acc.x, h0, l0); splitbf(acc.y, h1, l1);
        splitbf(acc.z, h2, l2); splitbf(acc.w, h3, l3);
        outh[o] = h0; outh[o + 1] = h1; outh[o + 2] = h2; outh[o + 3] = h3;
        outl[o] = l0; outl[o + 1] = l1; outl[o + 2] = l2; outl[o + 3] = l3;
    }
}

// strided copy reconstructing fp32 from hi+lo planes
__global__ void copy_hl(const __nv_bfloat16* __restrict__ h, const __nv_bfloat16* __restrict__ l,
                        float* __restrict__ dst, int ld, int valid, int rows) {
    long i = (long)blockIdx.x * blockDim.x + threadIdx.x;
    long total = (long)rows * valid;
    if (i >= total) return;
    int n = (int)(i / valid), f = (int)(i % valid);
    size_t o = (size_t)n * ld + f;
    dst[i] = __bfloat162float(h[o]) + __bfloat162float(l[o]);
}

// ---------------- host ----------------
template <typename T>
static T* sym(const void* s) { void* p; cudaGetSymbolAddress(&p, s); return (T*)p; }

static void run_gemm(cudaStream_t st, const __nv_bfloat16* Ah, const __nv_bfloat16* Al, int lda,
                     const __nv_bfloat16* Bh, const __nv_bfloat16* Bl, int Npad,
                     float* Cf, __nv_bfloat16* oH, __nv_bfloat16* oL,
                     const float* bias, int validN, int act,
                     int M, int Kpad) {
    dim3 grid(Npad >> 7, M >> 7);
    gemm_bf16x3<<<grid, 128, GSMEM, st>>>(Ah, Al, lda, Bh, Bl, Npad, Cf, Npad, oH, oL, bias, validN, act, Kpad);
}

extern "C" void kernel_launch(void* const* d_in, const int* in_sizes, int n_in,
                              void* d_out, int out_size) {
    const float* inputs = (const float*)d_in[0];
    const float* sent   = (const float*)d_in[5];
    const float* W_ha = (const float*)d_in[6];  const float* b_ha = (const float*)d_in[7];
    const float* W_da = (const float*)d_in[8];  const float* b_da = (const float*)d_in[9];
    const float* W_ht = (const float*)d_in[10]; const float* b_ht = (const float*)d_in[11];
    const float* W_dt = (const float*)d_in[12]; const float* b_dt = (const float*)d_in[13];
    const float* bilW = (const float*)d_in[14]; const float* bilb = (const float*)d_in[15];
    const float* c1aW = (const float*)d_in[16]; const float* c1ab = (const float*)d_in[17];
    const float* c2aW = (const float*)d_in[18]; const float* c2ab = (const float*)d_in[19];
    const float* c1rW = (const float*)d_in[20]; const float* c1rb = (const float*)d_in[21];
    const float* c2rW = (const float*)d_in[22]; const float* c2rb = (const float*)d_in[23];
    float* out = (float*)d_out;

    static cudaStream_t s2 = nullptr;
    static cudaEvent_t ev0, evT0, evT1, evJ;
    if (!s2) {
        cudaStreamCreateWithFlags(&s2, cudaStreamNonBlocking);
        cudaEventCreateWithFlags(&ev0, cudaEventDisableTiming);
        cudaEventCreateWithFlags(&evT0, cudaEventDisableTiming);
        cudaEventCreateWithFlags(&evT1, cudaEventDisableTiming);
        cudaEventCreateWithFlags(&evJ, cudaEventDisableTiming);
    }
    cudaStream_t ms = 0;

    cudaFuncSetAttribute(gemm_bf16x3, cudaFuncAttributeMaxDynamicSharedMemorySize, GSMEM);
    cudaFuncSetAttribute(bil_nt_bf16x3, cudaFuncAttributeMaxDynamicSharedMemorySize, BILSMEM);

    float* lg   = sym<float>(g_lg);
    float* xw   = sym<float>(g_xw);
    float* xwt  = sym<float>(g_xwt);
    __nv_bfloat16 *xH = sym<__nv_bfloat16>(g_xH), *xL = sym<__nv_bfloat16>(g_xL);
    __nv_bfloat16 *arcH = sym<__nv_bfloat16>(g_arcH), *arcL = sym<__nv_bfloat16>(g_arcL);
    __nv_bfloat16 *tagH = sym<__nv_bfloat16>(g_tagH), *tagL = sym<__nv_bfloat16>(g_tagL);
    __nv_bfloat16 *t1H = sym<__nv_bfloat16>(g_t1H), *t1L = sym<__nv_bfloat16>(g_t1L);
    __nv_bfloat16 *hH = sym<__nv_bfloat16>(g_hH), *hL = sym<__nv_bfloat16>(g_hL);
    __nv_bfloat16 *thH = sym<__nv_bfloat16>(g_thH), *thL = sym<__nv_bfloat16>(g_thL);
    __nv_bfloat16 *whaH = sym<__nv_bfloat16>(g_whaH), *whaL = sym<__nv_bfloat16>(g_whaL);
    __nv_bfloat16 *wdaH = sym<__nv_bfloat16>(g_wdaH), *wdaL = sym<__nv_bfloat16>(g_wdaL);
    __nv_bfloat16 *whtH = sym<__nv_bfloat16>(g_whtH), *whtL = sym<__nv_bfloat16>(g_whtL);
    __nv_bfloat16 *wdtH = sym<__nv_bfloat16>(g_wdtH), *wdtL = sym<__nv_bfloat16>(g_wdtL);
    __nv_bfloat16 *bilH = sym<__nv_bfloat16>(g_bilH), *bilL = sym<__nv_bfloat16>(g_bilL);
    __nv_bfloat16 *c1aH = sym<__nv_bfloat16>(g_c1aH), *c1aL = sym<__nv_bfloat16>(g_c1aL);
    __nv_bfloat16 *c2aH = sym<__nv_bfloat16>(g_c2aH), *c2aL = sym<__nv_bfloat16>(g_c2aL);
    __nv_bfloat16 *c1rH = sym<__nv_bfloat16>(g_c1rH), *c1rL = sym<__nv_bfloat16>(g_c1rL);
    __nv_bfloat16 *c2rH = sym<__nv_bfloat16>(g_c2rH), *c2rL = sym<__nv_bfloat16>(g_c2rL);

    __nv_bfloat16 *haH = arcH, *haL = arcL;
    __nv_bfloat16 *daH = arcH + (size_t)NROWS * ARCP, *daL = arcL + (size_t)NROWS * ARCP;
    __nv_bfloat16 *htH = tagH, *htL = tagL;
    __nv_bfloat16 *dtH = tagH + (size_t)NROWS * TAGP, *dtL = tagL + (size_t)NROWS * TAGP;

    // --- fused weight pack ---
    {
        PTab t;
        long base = 0;
        auto add = [&](int q, const float* src, __nv_bfloat16* hi, __nv_bfloat16* lo,
                       int Wr, int Wc, int ldw, int Kp, int Np) {
            t.j[q] = {src, hi, lo, Wr, Wc, ldw, Np, base, base + (long)Kp * Np};
            base += (long)Kp * Np;
        };
        add(0, W_ha, whaH, whaL, 768, 500, 500, 768, 512);
        add(1, W_da, wdaH, wdaL, 768, 500, 500, 768, 512);
        add(2, W_ht, whtH, whtL, 768, 100, 100, 768, 128);
        add(3, W_dt, wdtH, wdtL, 768, 100, 100, 768, 128);
        for (int k = 0; k < 3; k++)
            add(4 + k, bilW + (size_t)k * 501 * 501, bilH + (size_t)k * 512 * 512,
                bilL + (size_t)k * 512 * 512, 500, 501, 501, 512, 512);
        add(7, c1aW, c1aH, c1aL, 500, 500, 500, 512, 512);
        add(8, c2aW, c2aH, c2aL, 500, 500, 500, 512, 512);
        add(9, c1rW, c1rH, c1rL, 100, 100, 100, 128, 128);
        add(10, c2rW, c2rH, c2rL, 100, 100, 100, 128, 128);
        pack_all<<<(unsigned)((base + 255) / 256), 256, 0, ms>>>(t, base);
    }

    // --- x ---
    build_x_split<<<NROWS, 256, 0, ms>>>(inputs, sent, xH, xL);
    cudaEventRecord(ev0, ms);
    cudaStreamWaitEvent(s2, ev0, 0);

    run_gemm(ms, xH, xL, Dd, whaH, whaL, ARCP, nullptr, haH, haL, b_ha, ARCc, 1, NROWS, Dd);
    run_gemm(ms, xH, xL, Dd, wdaH, wdaL, ARCP, nullptr, daH, daL, b_da, ARCc, 1, NROWS, Dd);
    run_gemm(s2, xH, xL, Dd, whtH, whtL, TAGP, nullptr, htH, htL, b_ht, TAGc, 1, NROWS, Dd);
    run_gemm(s2, xH, xL, Dd, wdtH, wdtL, TAGP, nullptr, dtH, dtL, b_dt, TAGc, 1, NROWS, Dd);

    dim3 bilgrid(2, 2, Bb);
    int edgegrid = (Bb * 2 * SPc + 7) / 8;
    int smgrid = (NROWS + 7) / 8;
    cudaEvent_t evT[2] = {evT0, evT1};

    for (int k = 0; k < 2; k++) {
        run_gemm(ms, haH, haL, ARCP, bilH + (size_t)k * 512 * 512, bilL + (size_t)k * 512 * 512, ARCP,
                 nullptr, t1H, t1L, bilW + (size_t)k * 501 * 501 + (size_t)500 * 501, 501, 0, NROWS, ARCP);
        bil_nt_bf16x3<<<bilgrid, 128, BILSMEM, ms>>>(t1H, t1L, daH, daL, bilb, k, lg);
        bil_edge<<<edgegrid, 256, 0, ms>>>(t1H, t1L, daH, daL, bilb, k, lg);
        smax_topk<<<smgrid, 256, 0, ms>>>(lg);
        cudaEventRecord(evT[k], ms);
        cudaStreamWaitEvent(s2, evT[k], 0);

        // arc chain (main)
        run_gemm(ms, arcH, arcL, ARCP, c1aH, c1aL, ARCP, xw, nullptr, nullptr, nullptr, 0, 0, 2 * NROWS, ARCP);
        gcn_agg_split<<<2 * NROWS, 128, 0, ms>>>(xw, c1ab, hH, hL, ARCP, ARCc, 1);
        run_gemm(ms, hH, hL, ARCP, c2aH, c2aL, ARCP, xw, nullptr, nullptr, nullptr, 0, 0, 2 * NROWS, ARCP);
        gcn_agg_split<<<2 * NROWS, 128, 0, ms>>>(xw, c2ab, arcH, arcL, ARCP, ARCc, 0);
        // tag chain (s2)
        run_gemm(s2, tagH, tagL, TAGP, c1rH, c1rL, TAGP, xwt, nullptr, nullptr, nullptr, 0, 0, 2 * NROWS, TAGP);
        gcn_agg_split<<<2 * NROWS, 128, 0, s2>>>(xwt, c1rb, thH, thL, TAGP, TAGc, 1);
        run_gemm(s2, thH, thL, TAGP, c2rH, c2rL, TAGP, xwt, nullptr, nullptr, nullptr, 0, 0, 2 * NROWS, TAGP);
        gcn_agg_split<<<2 * NROWS, 128, 0, s2>>>(xwt, c2rb, tagH, tagL, TAGP, TAGc, 0);
    }

    // final bilinear -> d_out (main) ; tag output copies (s2)
    long arcN = (long)Bb * SPc * SPc;
    long tagN = (long)NROWS * TAGc;
    run_gemm(ms, haH, haL, ARCP, bilH + (size_t)2 * 512 * 512, bilL + (size_t)2 * 512 * 512, ARCP,
             nullptr, t1H, t1L, bilW + (size_t)2 * 501 * 501 + (size_t)500 * 501, 501, 0, NROWS, ARCP);
    bil_nt_bf16x3<<<bilgrid, 128, BILSMEM, ms>>>(t1H, t1L, daH, daL, bilb, 2, out);
    bil_edge<<<edgegrid, 256, 0, ms>>>(t1H, t1L, daH, daL, bilb, 2, out);

    copy_hl<<<(unsigned)((tagN + 255) / 256), 256, 0, s2>>>(htH, htL, out + arcN, TAGP, TAGc, NROWS);
    copy_hl<<<(unsigned)((tagN + 255) / 256), 256, 0, s2>>>(dtH, dtL, out + arcN + tagN, TAGP, TAGc, NROWS);

    cudaEventRecord(evJ, s2);
    cudaStreamWaitEvent(ms, evJ, 0);
}